// round 1
// baseline (speedup 1.0000x reference)
#include <cuda_runtime.h>

#define TILE_E 32
#define NEG_SLOPE 0.01f
#define LN_EPS 1e-5f

__device__ __forceinline__ float lrelu(float x) { return x > 0.f ? x : NEG_SLOPE * x; }

// ---------------------------------------------------------------------------
// Zero-fill (agg scratch lives inside d_out)
// ---------------------------------------------------------------------------
__global__ void zero_kernel(float4* __restrict__ p, long n4) {
    long i = (long)blockIdx.x * blockDim.x + threadIdx.x;
    long stride = (long)gridDim.x * blockDim.x;
    float4 z = make_float4(0.f, 0.f, 0.f, 0.f);
    for (; i < n4; i += stride) p[i] = z;
}

// ---------------------------------------------------------------------------
// Edge message + scatter:
//   agg[dst] += leaky_relu((x_src[s] * x_dst[d]) @ W + b)
// Block: 256 threads, tile of 32 edges x 128 cols. W cached in smem.
// Thread (ec=tid>>5, jc=tid&31) computes a 4-edge x 4-col register tile.
// ---------------------------------------------------------------------------
__global__ void __launch_bounds__(256, 2) msg_kernel(
    const float* __restrict__ xs, const float* __restrict__ xd,
    const float* __restrict__ W, const float* __restrict__ bias,
    const int* __restrict__ src, const int* __restrict__ dst,
    int E, float* __restrict__ agg)
{
    extern __shared__ float sm[];
    float* Wsh = sm;               // 128*128 floats (64 KB)
    float* Psh = sm + 128 * 128;   // 32*128 floats  (16 KB), edge-major
    __shared__ int s_src[TILE_E];
    __shared__ int s_dst[TILE_E];

    const int tid = threadIdx.x;
    const int jc = tid & 31;   // column group: cols 4*jc .. 4*jc+3
    const int ec = tid >> 5;   // edge group (warp id): edges 4*ec .. 4*ec+3

    // Load W into shared once per block (row-major: W[k][j])
    for (int i = tid; i < (128 * 128) / 4; i += 256)
        ((float4*)Wsh)[i] = ((const float4*)W)[i];

    const float4 b4 = ((const float4*)bias)[jc];

    const int numTiles = (E + TILE_E - 1) / TILE_E;
    for (int tile = blockIdx.x; tile < numTiles; tile += gridDim.x) {
        const int ebase = tile * TILE_E;
        __syncthreads();  // protect s_src/s_dst/Psh reuse across iterations
        if (tid < TILE_E) {
            int eg = ebase + tid;
            int s = 0, d = -1;
            if (eg < E) { s = src[eg]; d = dst[eg]; }
            s_src[tid] = s;
            s_dst[tid] = d;
        }
        __syncthreads();

        // Fill P[e][k] = xs[s][k] * xd[d][k]   (1024 float4s, 4 per thread)
        #pragma unroll
        for (int it = 0; it < 4; it++) {
            int idx = it * 256 + tid;        // 0..1023
            int e = idx >> 5;                // edge 0..31 (fixed per warp)
            int k4 = idx & 31;               // float4 index along features
            int s = s_src[e], d = s_dst[e];
            float4 p = make_float4(0.f, 0.f, 0.f, 0.f);
            if (d >= 0) {
                float4 a = ((const float4*)(xs + (size_t)s * 128))[k4];
                float4 c = ((const float4*)(xd + (size_t)d * 128))[k4];
                p.x = a.x * c.x; p.y = a.y * c.y;
                p.z = a.z * c.z; p.w = a.w * c.w;
            }
            ((float4*)(Psh + e * 128))[k4] = p;
        }
        __syncthreads();

        // GEMM: acc[e][c] = sum_k P[e][k] * W[k][4*jc+c]
        float acc[4][4];
        #pragma unroll
        for (int e = 0; e < 4; e++)
            #pragma unroll
            for (int c = 0; c < 4; c++) acc[e][c] = 0.f;

        const float* prow = Psh + (ec * 4) * 128;
        #pragma unroll 2
        for (int k = 0; k < 128; k += 4) {
            float4 w0 = ((const float4*)(Wsh + (k + 0) * 128))[jc];
            float4 w1 = ((const float4*)(Wsh + (k + 1) * 128))[jc];
            float4 w2 = ((const float4*)(Wsh + (k + 2) * 128))[jc];
            float4 w3 = ((const float4*)(Wsh + (k + 3) * 128))[jc];
            #pragma unroll
            for (int e = 0; e < 4; e++) {
                float4 p = *(const float4*)(prow + e * 128 + k);
                acc[e][0] += p.x * w0.x; acc[e][0] += p.y * w1.x;
                acc[e][0] += p.z * w2.x; acc[e][0] += p.w * w3.x;
                acc[e][1] += p.x * w0.y; acc[e][1] += p.y * w1.y;
                acc[e][1] += p.z * w2.y; acc[e][1] += p.w * w3.y;
                acc[e][2] += p.x * w0.z; acc[e][2] += p.y * w1.z;
                acc[e][2] += p.z * w2.z; acc[e][2] += p.w * w3.z;
                acc[e][3] += p.x * w0.w; acc[e][3] += p.y * w1.w;
                acc[e][3] += p.z * w2.w; acc[e][3] += p.w * w3.w;
            }
        }

        // Epilogue: bias + LeakyReLU + vector atomic scatter-add
        #pragma unroll
        for (int e = 0; e < 4; e++) {
            int le = ec * 4 + e;
            int dnode = s_dst[le];
            if (dnode < 0) continue;
            float m0 = lrelu(acc[e][0] + b4.x);
            float m1 = lrelu(acc[e][1] + b4.y);
            float m2 = lrelu(acc[e][2] + b4.z);
            float m3 = lrelu(acc[e][3] + b4.w);
            float* ptr = agg + (size_t)dnode * 128 + jc * 4;
            asm volatile("red.global.add.v4.f32 [%0], {%1, %2, %3, %4};"
                         :: "l"(ptr), "f"(m0), "f"(m1), "f"(m2), "f"(m3)
                         : "memory");
        }
    }
}

// ---------------------------------------------------------------------------
// In-place LayerNorm (over feature dim) + ReLU. One warp per node.
// ---------------------------------------------------------------------------
__global__ void ln_relu_kernel(float* __restrict__ x,
                               const float* __restrict__ w,
                               const float* __restrict__ b, int N)
{
    int gw = (int)((blockIdx.x * blockDim.x + threadIdx.x) >> 5);
    int lane = threadIdx.x & 31;
    if (gw >= N) return;

    float4 v = ((const float4*)(x + (size_t)gw * 128))[lane];
    float s = v.x + v.y + v.z + v.w;
    #pragma unroll
    for (int o = 16; o; o >>= 1) s += __shfl_xor_sync(0xffffffffu, s, o);
    float mu = s * (1.f / 128.f);

    float dx = v.x - mu, dy = v.y - mu, dz = v.z - mu, dw = v.w - mu;
    float q = dx * dx + dy * dy + dz * dz + dw * dw;
    #pragma unroll
    for (int o = 16; o; o >>= 1) q += __shfl_xor_sync(0xffffffffu, q, o);
    float rs = rsqrtf(q * (1.f / 128.f) + LN_EPS);

    float4 wv = ((const float4*)w)[lane];
    float4 bv = ((const float4*)b)[lane];
    float4 r;
    r.x = fmaxf(dx * rs * wv.x + bv.x, 0.f);
    r.y = fmaxf(dy * rs * wv.y + bv.y, 0.f);
    r.z = fmaxf(dz * rs * wv.z + bv.z, 0.f);
    r.w = fmaxf(dw * rs * wv.w + bv.w, 0.f);
    ((float4*)(x + (size_t)gw * 128))[lane] = r;
}

// ---------------------------------------------------------------------------
// Launch
// Inputs (metadata order):
//  0 x_user[100000*128] 1 x_item[50000*128]
//  2 W_ui[128*128] 3 b_ui[128] 4 W_iu[128*128] 5 b_iu[128]
//  6 ln_w_user 7 ln_b_user 8 ln_w_item 9 ln_b_item
//  10 edge_src_ui 11 edge_dst_ui 12 edge_src_iu 13 edge_dst_iu (int32)
// Output: [out_user (100000x128), out_item (50000x128)] fp32, concatenated.
// d_out doubles as the aggregation scratch (zero -> scatter -> LN in place).
// ---------------------------------------------------------------------------
extern "C" void kernel_launch(void* const* d_in, const int* in_sizes, int n_in,
                              void* d_out, int out_size)
{
    const float* x_user = (const float*)d_in[0];
    const float* x_item = (const float*)d_in[1];
    const float* W_ui   = (const float*)d_in[2];
    const float* b_ui   = (const float*)d_in[3];
    const float* W_iu   = (const float*)d_in[4];
    const float* b_iu   = (const float*)d_in[5];
    const float* lnw_u  = (const float*)d_in[6];
    const float* lnb_u  = (const float*)d_in[7];
    const float* lnw_i  = (const float*)d_in[8];
    const float* lnb_i  = (const float*)d_in[9];
    const int* es_ui = (const int*)d_in[10];
    const int* ed_ui = (const int*)d_in[11];
    const int* es_iu = (const int*)d_in[12];
    const int* ed_iu = (const int*)d_in[13];

    const int n_user = in_sizes[0] / 128;
    const int n_item = in_sizes[1] / 128;
    const int E_ui = in_sizes[10];
    const int E_iu = in_sizes[12];

    float* out = (float*)d_out;
    float* agg_user = out;                          // n_user x 128
    float* agg_item = out + (size_t)n_user * 128;   // n_item x 128

    // 1) zero the aggregation buffers (== whole d_out)
    long n4 = ((long)n_user + n_item) * 128 / 4;
    zero_kernel<<<4096, 256>>>((float4*)out, n4);

    // 2) edge message + scatter for both relations
    size_t smem = (size_t)(128 * 128 + TILE_E * 128) * sizeof(float);
    cudaFuncSetAttribute(msg_kernel,
                         cudaFuncAttributeMaxDynamicSharedMemorySize,
                         (int)smem);
    // user->item uses W_ui, aggregates at items
    msg_kernel<<<592, 256, smem>>>(x_user, x_item, W_ui, b_ui,
                                   es_ui, ed_ui, E_ui, agg_item);
    // item->user uses W_iu, aggregates at users
    msg_kernel<<<592, 256, smem>>>(x_item, x_user, W_iu, b_iu,
                                   es_iu, ed_iu, E_iu, agg_user);

    // 3) per-node LayerNorm + ReLU, in place
    ln_relu_kernel<<<(n_user + 7) / 8, 256>>>(agg_user, lnw_u, lnb_u, n_user);
    ln_relu_kernel<<<(n_item + 7) / 8, 256>>>(agg_item, lnw_i, lnb_i, n_item);

    (void)n_in; (void)out_size;
}

// round 2
// speedup vs baseline: 1.2704x; 1.2704x over previous
#include <cuda_runtime.h>

#define TILE_E 64          // edges per block tile (32 edge-pairs)
#define NEG_SLOPE 0.01f
#define LN_EPS 1e-5f

typedef unsigned long long ull;

__device__ __forceinline__ float lrelu(float x) { return x > 0.f ? x : NEG_SLOPE * x; }

// ---- packed f32x2 helpers (sm_100+ FFMA2 path; ptxas never auto-fuses) ----
__device__ __forceinline__ ull splat2(float x) {
    ull r; asm("mov.b64 %0, {%1, %1};" : "=l"(r) : "f"(x)); return r;
}
__device__ __forceinline__ ull fma2(ull a, ull b, ull c) {
    ull d; asm("fma.rn.f32x2 %0, %1, %2, %3;" : "=l"(d) : "l"(a), "l"(b), "l"(c));
    return d;
}
__device__ __forceinline__ float2 unpk2(ull v) {
    float2 f; asm("mov.b64 {%0, %1}, %2;" : "=f"(f.x), "=f"(f.y) : "l"(v)); return f;
}

// ---------------------------------------------------------------------------
// Zero-fill (agg scratch lives inside d_out)
// ---------------------------------------------------------------------------
__global__ void zero_kernel(float4* __restrict__ p, long n4) {
    long i = (long)blockIdx.x * blockDim.x + threadIdx.x;
    long stride = (long)gridDim.x * blockDim.x;
    float4 z = make_float4(0.f, 0.f, 0.f, 0.f);
    for (; i < n4; i += stride) p[i] = z;
}

// ---------------------------------------------------------------------------
// Edge message + scatter:  agg[dst] += leaky_relu((x_src[s]*x_dst[d]) @ W + b)
//
// Block: 256 threads (8 warps), tile of 64 edges x 128 cols.
// Shared: W (64KB) + P stored EDGE-PAIR-INTERLEAVED (32KB):
//   Ppair[ep][k] holds (p_{2ep,k}, p_{2ep+1,k}) as adjacent floats, so the
//   GEMM reads packed f32x2 operands straight from LDS (broadcast, cheap).
// Warp w computes edge-pairs 4w..4w+3; thread lane jc owns cols 4jc..4jc+3.
// Register tile: acc2[4 epairs][4 cols] packed along edges -> FFMA2 = 2 FMA.
// ---------------------------------------------------------------------------
__global__ void __launch_bounds__(256, 2) msg_kernel(
    const float* __restrict__ xs, const float* __restrict__ xd,
    const float* __restrict__ W, const float* __restrict__ bias,
    const int* __restrict__ src, const int* __restrict__ dst,
    int E, float* __restrict__ agg)
{
    extern __shared__ float sm[];
    float* Wsh   = sm;               // 128*128 floats (64 KB), row-major W[k][j]
    float* Ppair = sm + 128 * 128;   // 32 eps * 256 floats (32 KB)
    __shared__ int s_src[TILE_E];
    __shared__ int s_dst[TILE_E];

    const int tid = threadIdx.x;
    const int jc  = tid & 31;   // column group: cols 4*jc .. 4*jc+3
    const int wid = tid >> 5;   // warp id: edge-pairs 4*wid .. 4*wid+3

    // Load W into shared once per block
    for (int i = tid; i < (128 * 128) / 4; i += 256)
        ((float4*)Wsh)[i] = ((const float4*)W)[i];

    const float4 b4 = ((const float4*)bias)[jc];

    const int numTiles = (E + TILE_E - 1) / TILE_E;
    for (int tile = blockIdx.x; tile < numTiles; tile += gridDim.x) {
        __syncthreads();  // protect s_src/s_dst/Ppair reuse across iterations
        if (tid < TILE_E) {
            int eg = tile * TILE_E + tid;
            int s = 0, d = -1;
            if (eg < E) { s = src[eg]; d = dst[eg]; }
            s_src[tid] = s;
            s_dst[tid] = d;
        }
        __syncthreads();

        // ---- Fill Ppair: 32 eps x 32 k-quads = 1024 tasks, 4 per thread ----
        #pragma unroll
        for (int it = 0; it < 4; it++) {
            int idx = it * 256 + tid;
            int ep = idx >> 5;          // constant across warp -> coalesced LDG
            int kq = idx & 31;          // = lane
            int e0 = 2 * ep, e1 = e0 + 1;
            int s0 = s_src[e0], d0 = s_dst[e0];
            int s1 = s_src[e1], d1 = s_dst[e1];
            float4 p0 = make_float4(0.f, 0.f, 0.f, 0.f);
            float4 p1 = p0;
            if (d0 >= 0) {
                float4 a = ((const float4*)(xs + (size_t)s0 * 128))[kq];
                float4 c = ((const float4*)(xd + (size_t)d0 * 128))[kq];
                p0.x = a.x * c.x; p0.y = a.y * c.y;
                p0.z = a.z * c.z; p0.w = a.w * c.w;
            }
            if (d1 >= 0) {
                float4 a = ((const float4*)(xs + (size_t)s1 * 128))[kq];
                float4 c = ((const float4*)(xd + (size_t)d1 * 128))[kq];
                p1.x = a.x * c.x; p1.y = a.y * c.y;
                p1.z = a.z * c.z; p1.w = a.w * c.w;
            }
            float* dp = Ppair + ep * 256 + kq * 8;  // bytes: ep*1024 + kq*32
            ((float4*)dp)[0] = make_float4(p0.x, p1.x, p0.y, p1.y);
            ((float4*)dp)[1] = make_float4(p0.z, p1.z, p0.w, p1.w);
        }
        __syncthreads();

        // ---- GEMM: acc2[ep][c] = sum_k Ppair(ep,k) * W[k][4jc+c] ----
        ull acc[4][4];
        #pragma unroll
        for (int ep = 0; ep < 4; ep++)
            #pragma unroll
            for (int c = 0; c < 4; c++) acc[ep][c] = 0ull;  // bits of (0.f,0.f)

        #pragma unroll 2
        for (int k = 0; k < 128; k += 4) {
            float4 w0 = ((const float4*)(Wsh + (k + 0) * 128))[jc];
            float4 w1 = ((const float4*)(Wsh + (k + 1) * 128))[jc];
            float4 w2 = ((const float4*)(Wsh + (k + 2) * 128))[jc];
            float4 w3 = ((const float4*)(Wsh + (k + 3) * 128))[jc];
            // hoisted splats: 16 ALU movs reused across 4 edge-pairs
            ull sw[4][4];
            sw[0][0] = splat2(w0.x); sw[0][1] = splat2(w0.y);
            sw[0][2] = splat2(w0.z); sw[0][3] = splat2(w0.w);
            sw[1][0] = splat2(w1.x); sw[1][1] = splat2(w1.y);
            sw[1][2] = splat2(w1.z); sw[1][3] = splat2(w1.w);
            sw[2][0] = splat2(w2.x); sw[2][1] = splat2(w2.y);
            sw[2][2] = splat2(w2.z); sw[2][3] = splat2(w2.w);
            sw[3][0] = splat2(w3.x); sw[3][1] = splat2(w3.y);
            sw[3][2] = splat2(w3.z); sw[3][3] = splat2(w3.w);

            #pragma unroll
            for (int ep = 0; ep < 4; ep++) {
                const float* pr = Ppair + (4 * wid + ep) * 256 + k * 2;
                ulonglong2 q0 = ((const ulonglong2*)pr)[0];  // k, k+1 pairs
                ulonglong2 q1 = ((const ulonglong2*)pr)[1];  // k+2, k+3 pairs
                acc[ep][0] = fma2(q0.x, sw[0][0], acc[ep][0]);
                acc[ep][1] = fma2(q0.x, sw[0][1], acc[ep][1]);
                acc[ep][2] = fma2(q0.x, sw[0][2], acc[ep][2]);
                acc[ep][3] = fma2(q0.x, sw[0][3], acc[ep][3]);
                acc[ep][0] = fma2(q0.y, sw[1][0], acc[ep][0]);
                acc[ep][1] = fma2(q0.y, sw[1][1], acc[ep][1]);
                acc[ep][2] = fma2(q0.y, sw[1][2], acc[ep][2]);
                acc[ep][3] = fma2(q0.y, sw[1][3], acc[ep][3]);
                acc[ep][0] = fma2(q1.x, sw[2][0], acc[ep][0]);
                acc[ep][1] = fma2(q1.x, sw[2][1], acc[ep][1]);
                acc[ep][2] = fma2(q1.x, sw[2][2], acc[ep][2]);
                acc[ep][3] = fma2(q1.x, sw[2][3], acc[ep][3]);
                acc[ep][0] = fma2(q1.y, sw[3][0], acc[ep][0]);
                acc[ep][1] = fma2(q1.y, sw[3][1], acc[ep][1]);
                acc[ep][2] = fma2(q1.y, sw[3][2], acc[ep][2]);
                acc[ep][3] = fma2(q1.y, sw[3][3], acc[ep][3]);
            }
        }

        // ---- Epilogue: bias + LeakyReLU + vector atomic scatter ----
        #pragma unroll
        for (int ep = 0; ep < 4; ep++) {
            int g = 4 * wid + ep;
            int dn0 = s_dst[2 * g];
            int dn1 = s_dst[2 * g + 1];
            float2 v0 = unpk2(acc[ep][0]);
            float2 v1 = unpk2(acc[ep][1]);
            float2 v2 = unpk2(acc[ep][2]);
            float2 v3 = unpk2(acc[ep][3]);
            if (dn0 >= 0) {
                float m0 = lrelu(v0.x + b4.x), m1 = lrelu(v1.x + b4.y);
                float m2 = lrelu(v2.x + b4.z), m3 = lrelu(v3.x + b4.w);
                float* ptr = agg + (size_t)dn0 * 128 + jc * 4;
                asm volatile("red.global.add.v4.f32 [%0], {%1, %2, %3, %4};"
                             :: "l"(ptr), "f"(m0), "f"(m1), "f"(m2), "f"(m3)
                             : "memory");
            }
            if (dn1 >= 0) {
                float m0 = lrelu(v0.y + b4.x), m1 = lrelu(v1.y + b4.y);
                float m2 = lrelu(v2.y + b4.z), m3 = lrelu(v3.y + b4.w);
                float* ptr = agg + (size_t)dn1 * 128 + jc * 4;
                asm volatile("red.global.add.v4.f32 [%0], {%1, %2, %3, %4};"
                             :: "l"(ptr), "f"(m0), "f"(m1), "f"(m2), "f"(m3)
                             : "memory");
            }
        }
    }
}

// ---------------------------------------------------------------------------
// In-place LayerNorm (over feature dim) + ReLU. One warp per node.
// ---------------------------------------------------------------------------
__global__ void ln_relu_kernel(float* __restrict__ x,
                               const float* __restrict__ w,
                               const float* __restrict__ b, int N)
{
    int gw = (int)((blockIdx.x * blockDim.x + threadIdx.x) >> 5);
    int lane = threadIdx.x & 31;
    if (gw >= N) return;

    float4 v = ((const float4*)(x + (size_t)gw * 128))[lane];
    float s = v.x + v.y + v.z + v.w;
    #pragma unroll
    for (int o = 16; o; o >>= 1) s += __shfl_xor_sync(0xffffffffu, s, o);
    float mu = s * (1.f / 128.f);

    float dx = v.x - mu, dy = v.y - mu, dz = v.z - mu, dw = v.w - mu;
    float q = dx * dx + dy * dy + dz * dz + dw * dw;
    #pragma unroll
    for (int o = 16; o; o >>= 1) q += __shfl_xor_sync(0xffffffffu, q, o);
    float rs = rsqrtf(q * (1.f / 128.f) + LN_EPS);

    float4 wv = ((const float4*)w)[lane];
    float4 bv = ((const float4*)b)[lane];
    float4 r;
    r.x = fmaxf(dx * rs * wv.x + bv.x, 0.f);
    r.y = fmaxf(dy * rs * wv.y + bv.y, 0.f);
    r.z = fmaxf(dz * rs * wv.z + bv.z, 0.f);
    r.w = fmaxf(dw * rs * wv.w + bv.w, 0.f);
    ((float4*)(x + (size_t)gw * 128))[lane] = r;
}

// ---------------------------------------------------------------------------
// Launch (input order per metadata; d_out doubles as aggregation scratch)
// ---------------------------------------------------------------------------
extern "C" void kernel_launch(void* const* d_in, const int* in_sizes, int n_in,
                              void* d_out, int out_size)
{
    const float* x_user = (const float*)d_in[0];
    const float* x_item = (const float*)d_in[1];
    const float* W_ui   = (const float*)d_in[2];
    const float* b_ui   = (const float*)d_in[3];
    const float* W_iu   = (const float*)d_in[4];
    const float* b_iu   = (const float*)d_in[5];
    const float* lnw_u  = (const float*)d_in[6];
    const float* lnb_u  = (const float*)d_in[7];
    const float* lnw_i  = (const float*)d_in[8];
    const float* lnb_i  = (const float*)d_in[9];
    const int* es_ui = (const int*)d_in[10];
    const int* ed_ui = (const int*)d_in[11];
    const int* es_iu = (const int*)d_in[12];
    const int* ed_iu = (const int*)d_in[13];

    const int n_user = in_sizes[0] / 128;
    const int n_item = in_sizes[1] / 128;
    const int E_ui = in_sizes[10];
    const int E_iu = in_sizes[12];

    float* out = (float*)d_out;
    float* agg_user = out;                          // n_user x 128
    float* agg_item = out + (size_t)n_user * 128;   // n_item x 128

    // 1) zero the aggregation buffers (== whole d_out)
    long n4 = ((long)n_user + n_item) * 128 / 4;
    zero_kernel<<<4096, 256>>>((float4*)out, n4);

    // 2) edge message + scatter for both relations
    size_t smem = (size_t)(128 * 128 + 32 * 256) * sizeof(float);  // 96 KB
    cudaFuncSetAttribute(msg_kernel,
                         cudaFuncAttributeMaxDynamicSharedMemorySize,
                         (int)smem);
    msg_kernel<<<592, 256, smem>>>(x_user, x_item, W_ui, b_ui,
                                   es_ui, ed_ui, E_ui, agg_item);
    msg_kernel<<<592, 256, smem>>>(x_item, x_user, W_iu, b_iu,
                                   es_iu, ed_iu, E_iu, agg_user);

    // 3) per-node LayerNorm + ReLU, in place
    ln_relu_kernel<<<(n_user + 7) / 8, 256>>>(agg_user, lnw_u, lnb_u, n_user);
    ln_relu_kernel<<<(n_item + 7) / 8, 256>>>(agg_item, lnw_i, lnb_i, n_item);

    (void)n_in; (void)out_size;
}

// round 4
// speedup vs baseline: 1.3039x; 1.0264x over previous
#include <cuda_runtime.h>
#include <cuda_bf16.h>
#include <cstdint>

#define NEG_SLOPE 0.01f
#define LN_EPS 1e-5f

__device__ __forceinline__ float lrelu(float x) { return fmaxf(x, NEG_SLOPE * x); }

__device__ __forceinline__ uint32_t smem_u32(const void* p) {
    uint32_t a;
    asm("{ .reg .u64 t; cvta.to.shared.u64 t, %1; cvt.u32.u64 %0, t; }" : "=r"(a) : "l"(p));
    return a;
}

__device__ __forceinline__ void ldm_x4(uint32_t r[4], uint32_t a) {
    asm volatile("ldmatrix.sync.aligned.m8n8.x4.shared.b16 {%0,%1,%2,%3}, [%4];"
                 : "=r"(r[0]), "=r"(r[1]), "=r"(r[2]), "=r"(r[3]) : "r"(a) : "memory");
}
__device__ __forceinline__ void ldm_x2(uint32_t r[2], uint32_t a) {
    asm volatile("ldmatrix.sync.aligned.m8n8.x2.shared.b16 {%0,%1}, [%2];"
                 : "=r"(r[0]), "=r"(r[1]) : "r"(a) : "memory");
}
__device__ __forceinline__ void mma_bf16(float* d, const uint32_t* a, const uint32_t* b) {
    asm volatile("mma.sync.aligned.m16n8k16.row.col.f32.bf16.bf16.f32 "
                 "{%0,%1,%2,%3}, {%4,%5,%6,%7}, {%8,%9}, {%0,%1,%2,%3};"
                 : "+f"(d[0]), "+f"(d[1]), "+f"(d[2]), "+f"(d[3])
                 : "r"(a[0]), "r"(a[1]), "r"(a[2]), "r"(a[3]), "r"(b[0]), "r"(b[1]));
}

// ============================ kernels ============================
__global__ void zero_kernel(float4* __restrict__ p, long n4) {
    long i = (long)blockIdx.x * blockDim.x + threadIdx.x;
    long stride = (long)gridDim.x * blockDim.x;
    float4 z = make_float4(0.f, 0.f, 0.f, 0.f);
    for (; i < n4; i += stride) p[i] = z;
}

// Shared tiles: row-major [rows][128 bf16] = 256 B/row, XOR-16B swizzle:
//   byte_addr(r, cb) = r*256 + (cb ^ ((r&7)<<4))
// B (= W^T so mma col-major operand works): Bt[n][k], hi at 0, lo at 32768.
// A (edge products P[e][k]): hi at 65536, lo at 98304.
#define SM_BHI 0
#define SM_BLO 32768
#define SM_AHI 65536
#define SM_ALO 98304
#define SMEM_DYN 131072

__global__ void __launch_bounds__(256) msg_kernel(
    const float* __restrict__ xs, const float* __restrict__ xd,
    const float* __restrict__ W, const float* __restrict__ bias,
    const int* __restrict__ src, const int* __restrict__ dst,
    int E, float* __restrict__ agg)
{
    extern __shared__ char smc[];
    __shared__ int s_src[128];
    __shared__ int s_dst[128];

    const int tid  = threadIdx.x;
    const int wid  = tid >> 5;
    const int lane = tid & 31;
    const int warpM = wid >> 1;          // 4 groups of 32 edges
    const int warpN = wid & 1;           // 2 groups of 64 cols
    const uint32_t sbase = smem_u32(smc);

    // ---- one-time W prep: Bt[n][k] = W[k][n], bf16 hi + residual lo ----
    for (int idx = tid; idx < 128 * 128; idx += 256) {
        int k = idx >> 7, n = idx & 127;      // coalesced read over W row k
        float w = W[idx];
        __nv_bfloat16 hb = __float2bfloat16(w);
        float hf = __bfloat162float(hb);
        __nv_bfloat16 lb = __float2bfloat16(w - hf);
        uint32_t off = (uint32_t)n * 256u + (((uint32_t)k * 2u) ^ (uint32_t)((n & 7) << 4));
        *(__nv_bfloat16*)(smc + SM_BHI + off) = hb;
        *(__nv_bfloat16*)(smc + SM_BLO + off) = lb;
    }

    // per-thread bias regs for epilogue (cols 2c, 2c+1 of each of 8 n-blocks)
    float bb0[8], bb1[8];
    #pragma unroll
    for (int nb = 0; nb < 8; nb++) {
        int cb = warpN * 64 + nb * 8 + 2 * (lane & 3);
        bb0[nb] = bias[cb];
        bb1[nb] = bias[cb + 1];
    }

    // lane-fixed ldmatrix address components
    const uint32_t xr = (uint32_t)((lane & 7) << 4);     // swizzle xor (A and B)
    // A: x4 tiles: t0 r0-7/k0-7, t1 r8-15/k0-7, t2 r0-7/k8-15, t3 r8-15/k8-15
    const int rA_lo = warpM * 32 + ((lane >> 3) & 1) * 8 + (lane & 7);  // + ms*16
    const uint32_t kselA = (uint32_t)((lane >> 4) * 16);
    // B: x2 tiles from lanes 0-15: n rows 0-7 at k0, n rows 0-7 at k8
    const int l15 = lane & 15;
    const int nB_base = warpN * 64 + (l15 & 7);                         // + nb*8
    const uint32_t kselB = (uint32_t)(((l15 >> 3) & 1) * 16);

    const int numTiles = (E + 127) >> 7;
    for (int tile = blockIdx.x; tile < numTiles; tile += gridDim.x) {
        __syncthreads();   // prior tile's mma/epilogue done with A + s_dst

        if (tid < 128) {
            int eg = tile * 128 + tid;
            int s = 0, d = -1;
            if (eg < E) { s = src[eg]; d = dst[eg]; }
            s_src[tid] = s;
            s_dst[tid] = d;
        }
        __syncthreads();

        // ---- fill A: P = xs[s]*xd[d], split bf16 hi/lo, swizzled ----
        #pragma unroll
        for (int it = 0; it < 16; it++) {
            int idx = it * 256 + tid;        // 0..4095
            int e  = idx >> 5;               // warp-uniform edge row
            int kq = idx & 31;               // float4 index along k
            int s = s_src[e], d = s_dst[e];
            float4 p = make_float4(0.f, 0.f, 0.f, 0.f);
            if (d >= 0) {
                float4 a = ((const float4*)(xs + (size_t)s * 128))[kq];
                float4 c = ((const float4*)(xd + (size_t)d * 128))[kq];
                p.x = a.x * c.x; p.y = a.y * c.y;
                p.z = a.z * c.z; p.w = a.w * c.w;
            }
            uint32_t h01, h23;   // low half = even k, high half = odd k
            asm("cvt.rn.bf16x2.f32 %0, %1, %2;" : "=r"(h01) : "f"(p.y), "f"(p.x));
            asm("cvt.rn.bf16x2.f32 %0, %1, %2;" : "=r"(h23) : "f"(p.w), "f"(p.z));
            float hx = __uint_as_float(h01 << 16);
            float hy = __uint_as_float(h01 & 0xffff0000u);
            float hz = __uint_as_float(h23 << 16);
            float hw = __uint_as_float(h23 & 0xffff0000u);
            uint32_t l01, l23;
            asm("cvt.rn.bf16x2.f32 %0, %1, %2;" : "=r"(l01) : "f"(p.y - hy), "f"(p.x - hx));
            asm("cvt.rn.bf16x2.f32 %0, %1, %2;" : "=r"(l23) : "f"(p.w - hw), "f"(p.z - hz));
            uint32_t off = (uint32_t)e * 256u + (((uint32_t)kq * 8u) ^ (uint32_t)((e & 7) << 4));
            *(uint2*)(smc + SM_AHI + off) = make_uint2(h01, h23);
            *(uint2*)(smc + SM_ALO + off) = make_uint2(l01, l23);
        }
        __syncthreads();

        // ---- warp-tile GEMM: acc[ms 2][nb 8][4], 3-pass split bf16 ----
        float acc[2][8][4];
        #pragma unroll
        for (int ms = 0; ms < 2; ms++)
            #pragma unroll
            for (int nb = 0; nb < 8; nb++)
                #pragma unroll
                for (int q = 0; q < 4; q++) acc[ms][nb][q] = 0.f;

        #pragma unroll
        for (int ks = 0; ks < 8; ks++) {
            uint32_t Ah[2][4], Al[2][4];
            #pragma unroll
            for (int ms = 0; ms < 2; ms++) {
                uint32_t r = (uint32_t)(rA_lo + ms * 16);
                uint32_t kb = (uint32_t)(ks * 32) + kselA;
                uint32_t off = r * 256u + (kb ^ xr);
                ldm_x4(Ah[ms], sbase + SM_AHI + off);
                ldm_x4(Al[ms], sbase + SM_ALO + off);
            }
            #pragma unroll
            for (int nb = 0; nb < 8; nb++) {
                uint32_t n = (uint32_t)(nB_base + nb * 8);
                uint32_t kb = (uint32_t)(ks * 32) + kselB;
                uint32_t off = n * 256u + (kb ^ xr);
                uint32_t Bh[2], Bl[2];
                ldm_x2(Bh, sbase + SM_BHI + off);
                ldm_x2(Bl, sbase + SM_BLO + off);
                #pragma unroll
                for (int ms = 0; ms < 2; ms++) {
                    mma_bf16(acc[ms][nb], Ah[ms], Bh);
                    mma_bf16(acc[ms][nb], Ah[ms], Bl);
                    mma_bf16(acc[ms][nb], Al[ms], Bh);
                }
            }
        }

        // ---- epilogue: bias + LeakyReLU + shfl-pair into red.v4 ----
        #pragma unroll
        for (int ms = 0; ms < 2; ms++) {
            int e_lo = warpM * 32 + ms * 16 + (lane >> 2);
            int dn0 = s_dst[e_lo];
            int dn1 = s_dst[e_lo + 8];
            #pragma unroll
            for (int nb = 0; nb < 8; nb++) {
                float m0 = lrelu(acc[ms][nb][0] + bb0[nb]);
                float m1 = lrelu(acc[ms][nb][1] + bb1[nb]);
                float m2 = lrelu(acc[ms][nb][2] + bb0[nb]);
                float m3 = lrelu(acc[ms][nb][3] + bb1[nb]);
                float s0 = __shfl_xor_sync(0xffffffffu, m0, 1);
                float s1 = __shfl_xor_sync(0xffffffffu, m1, 1);
                float s2 = __shfl_xor_sync(0xffffffffu, m2, 1);
                float s3 = __shfl_xor_sync(0xffffffffu, m3, 1);
                if ((lane & 1) == 0) {
                    int cb = warpN * 64 + nb * 8 + 2 * (lane & 3);  // 0 or 4 offset
                    if (dn0 >= 0) {
                        float* ptr = agg + (size_t)dn0 * 128 + cb;
                        asm volatile("red.global.add.v4.f32 [%0], {%1, %2, %3, %4};"
                                     :: "l"(ptr), "f"(m0), "f"(m1), "f"(s0), "f"(s1)
                                     : "memory");
                    }
                    if (dn1 >= 0) {
                        float* ptr = agg + (size_t)dn1 * 128 + cb;
                        asm volatile("red.global.add.v4.f32 [%0], {%1, %2, %3, %4};"
                                     :: "l"(ptr), "f"(m2), "f"(m3), "f"(s2), "f"(s3)
                                     : "memory");
                    }
                }
            }
        }
    }
}

// ---------------------------------------------------------------------------
// In-place LayerNorm + ReLU. One warp per node.
// ---------------------------------------------------------------------------
__global__ void ln_relu_kernel(float* __restrict__ x,
                               const float* __restrict__ w,
                               const float* __restrict__ b, int N)
{
    int gw = (int)((blockIdx.x * blockDim.x + threadIdx.x) >> 5);
    int lane = threadIdx.x & 31;
    if (gw >= N) return;

    float4 v = ((const float4*)(x + (size_t)gw * 128))[lane];
    float s = v.x + v.y + v.z + v.w;
    #pragma unroll
    for (int o = 16; o; o >>= 1) s += __shfl_xor_sync(0xffffffffu, s, o);
    float mu = s * (1.f / 128.f);

    float dx = v.x - mu, dy = v.y - mu, dz = v.z - mu, dw = v.w - mu;
    float q = dx * dx + dy * dy + dz * dz + dw * dw;
    #pragma unroll
    for (int o = 16; o; o >>= 1) q += __shfl_xor_sync(0xffffffffu, q, o);
    float rs = rsqrtf(q * (1.f / 128.f) + LN_EPS);

    float4 wv = ((const float4*)w)[lane];
    float4 bv = ((const float4*)b)[lane];
    float4 r;
    r.x = fmaxf(dx * rs * wv.x + bv.x, 0.f);
    r.y = fmaxf(dy * rs * wv.y + bv.y, 0.f);
    r.z = fmaxf(dz * rs * wv.z + bv.z, 0.f);
    r.w = fmaxf(dw * rs * wv.w + bv.w, 0.f);
    ((float4*)(x + (size_t)gw * 128))[lane] = r;
}

// ---------------------------------------------------------------------------
extern "C" void kernel_launch(void* const* d_in, const int* in_sizes, int n_in,
                              void* d_out, int out_size)
{
    const float* x_user = (const float*)d_in[0];
    const float* x_item = (const float*)d_in[1];
    const float* W_ui   = (const float*)d_in[2];
    const float* b_ui   = (const float*)d_in[3];
    const float* W_iu   = (const float*)d_in[4];
    const float* b_iu   = (const float*)d_in[5];
    const float* lnw_u  = (const float*)d_in[6];
    const float* lnb_u  = (const float*)d_in[7];
    const float* lnw_i  = (const float*)d_in[8];
    const float* lnb_i  = (const float*)d_in[9];
    const int* es_ui = (const int*)d_in[10];
    const int* ed_ui = (const int*)d_in[11];
    const int* es_iu = (const int*)d_in[12];
    const int* ed_iu = (const int*)d_in[13];

    const int n_user = in_sizes[0] / 128;
    const int n_item = in_sizes[1] / 128;
    const int E_ui = in_sizes[10];
    const int E_iu = in_sizes[12];

    float* out = (float*)d_out;
    float* agg_user = out;
    float* agg_item = out + (size_t)n_user * 128;

    long n4 = ((long)n_user + n_item) * 128 / 4;
    zero_kernel<<<4096, 256>>>((float4*)out, n4);

    cudaFuncSetAttribute(msg_kernel,
                         cudaFuncAttributeMaxDynamicSharedMemorySize, SMEM_DYN);
    msg_kernel<<<148, 256, SMEM_DYN>>>(x_user, x_item, W_ui, b_ui,
                                       es_ui, ed_ui, E_ui, agg_item);
    msg_kernel<<<148, 256, SMEM_DYN>>>(x_item, x_user, W_iu, b_iu,
                                       es_iu, ed_iu, E_iu, agg_user);

    ln_relu_kernel<<<(n_user + 7) / 8, 256>>>(agg_user, lnw_u, lnb_u, n_user);
    ln_relu_kernel<<<(n_item + 7) / 8, 256>>>(agg_item, lnw_i, lnb_i, n_item);

    (void)n_in; (void)out_size;
}

// round 5
// speedup vs baseline: 1.4152x; 1.0853x over previous
#include <cuda_runtime.h>
#include <cuda_bf16.h>
#include <cstdint>

#define NEG_SLOPE 0.01f
#define LN_EPS 1e-5f

__device__ __forceinline__ float lrelu(float x) { return fmaxf(x, NEG_SLOPE * x); }

__device__ __forceinline__ uint32_t smem_u32(const void* p) {
    uint32_t a;
    asm("{ .reg .u64 t; cvta.to.shared.u64 t, %1; cvt.u32.u64 %0, t; }" : "=r"(a) : "l"(p));
    return a;
}
__device__ __forceinline__ void ldm_x4(uint32_t r[4], uint32_t a) {
    asm volatile("ldmatrix.sync.aligned.m8n8.x4.shared.b16 {%0,%1,%2,%3}, [%4];"
                 : "=r"(r[0]), "=r"(r[1]), "=r"(r[2]), "=r"(r[3]) : "r"(a) : "memory");
}
__device__ __forceinline__ void mma_bf16(float* d, const uint32_t* a, const uint32_t* b) {
    asm volatile("mma.sync.aligned.m16n8k16.row.col.f32.bf16.bf16.f32 "
                 "{%0,%1,%2,%3}, {%4,%5,%6,%7}, {%8,%9}, {%0,%1,%2,%3};"
                 : "+f"(d[0]), "+f"(d[1]), "+f"(d[2]), "+f"(d[3])
                 : "r"(a[0]), "r"(a[1]), "r"(a[2]), "r"(a[3]), "r"(b[0]), "r"(b[1]));
}
#define GBAR(g) asm volatile("bar.sync %0, %1;" :: "r"((g) + 1), "r"(128) : "memory")

// ============================ kernels ============================
__global__ void zero_kernel(float4* __restrict__ p, long n4) {
    long i = (long)blockIdx.x * blockDim.x + threadIdx.x;
    long stride = (long)gridDim.x * blockDim.x;
    float4 z = make_float4(0.f, 0.f, 0.f, 0.f);
    for (; i < n4; i += stride) p[i] = z;
}

// Shared layout (row-major [row][128 bf16] tiles, 256B rows, XOR-16B swizzle
//   byte(r, cb) = r*256 + (cb ^ ((r&7)<<4)) ):
//  B_hi 0, B_lo 32768 (Bt[n][k] = W[k][n])
//  A group0: hi 65536, lo 98304; group1: hi 131072, lo 163840
//  bias 196608
#define SM_BHI 0
#define SM_BLO 32768
#define SM_A(g, part) (65536 + (g) * 65536 + (part) * 32768)
#define SM_BIAS 196608
#define SMEM_DYN (196608 + 512)

__global__ void __launch_bounds__(256, 1) msg_kernel(
    const float* __restrict__ xs, const float* __restrict__ xd,
    const float* __restrict__ W, const float* __restrict__ bias,
    const int* __restrict__ src, const int* __restrict__ dst,
    int E, float* __restrict__ agg)
{
    extern __shared__ char smc[];
    __shared__ int s_src[2][128];
    __shared__ int s_dst[2][128];

    const int tid  = threadIdx.x;
    const int wid  = tid >> 5;
    const int lane = tid & 31;
    const int g    = wid >> 2;          // warp-group 0/1
    const int gtid = tid & 127;         // thread id within group
    const int warpM = wid & 3;          // 32-edge slice within group's tile
    const uint32_t sbase = smem_u32(smc);

    // ---- one-time W prep: Bt[n][k] = W[k][n], bf16 hi + residual lo ----
    for (int idx = tid; idx < 128 * 128; idx += 256) {
        int k = idx >> 7, n = idx & 127;
        float w = W[idx];
        __nv_bfloat16 hb = __float2bfloat16(w);
        float hf = __bfloat162float(hb);
        __nv_bfloat16 lb = __float2bfloat16(w - hf);
        uint32_t off = (uint32_t)n * 256u + (((uint32_t)k * 2u) ^ (uint32_t)((n & 7) << 4));
        *(__nv_bfloat16*)(smc + SM_BHI + off) = hb;
        *(__nv_bfloat16*)(smc + SM_BLO + off) = lb;
    }
    if (tid < 128) ((float*)(smc + SM_BIAS))[tid] = bias[tid];
    __syncthreads();
    const float* bias_sh = (const float*)(smc + SM_BIAS);

    // lane-fixed ldmatrix address components
    const uint32_t xr = (uint32_t)((lane & 7) << 4);
    const int rA_lo = warpM * 32 + ((lane >> 3) & 1) * 8 + (lane & 7);
    const uint32_t kselA = (uint32_t)((lane >> 4) * 16);
    // B x4: m0/m1 = rows n0..n0+7 at k0/k8; m2/m3 = rows n0+8..n0+15 at k0/k8
    const int rB = ((lane >> 4) & 1) * 8 + (lane & 7);
    const uint32_t kselB = (uint32_t)(((lane >> 3) & 1) * 16);

    char* Ahc = smc + SM_A(g, 0);
    char* Alc = smc + SM_A(g, 1);
    const uint32_t AhU = sbase + SM_A(g, 0);
    const uint32_t AlU = sbase + SM_A(g, 1);

    const int numTiles = (E + 127) >> 7;
    const int stride = (int)gridDim.x * 2;
    for (int tile = blockIdx.x * 2 + g; tile < numTiles; tile += stride) {
        GBAR(g);   // group's prior MMA/epilogue done with A + s_dst

        {   // ---- load edge indices (group's 128 threads) ----
            int eg = tile * 128 + gtid;
            int s = 0, d = -1;
            if (eg < E) { s = src[eg]; d = dst[eg]; }
            s_src[g][gtid] = s;
            s_dst[g][gtid] = d;
        }
        GBAR(g);

        // ---- fill A: P = xs[s]*xd[d], split bf16 hi/lo, swizzled ----
        #pragma unroll
        for (int it = 0; it < 32; it++) {
            int idx = it * 128 + gtid;       // 0..4095
            int e  = idx >> 5;               // warp-uniform edge row
            int kq = idx & 31;               // float4 index along k
            int s = s_src[g][e], d = s_dst[g][e];
            float4 p = make_float4(0.f, 0.f, 0.f, 0.f);
            if (d >= 0) {
                float4 a = ((const float4*)(xs + (size_t)s * 128))[kq];
                float4 c = ((const float4*)(xd + (size_t)d * 128))[kq];
                p.x = a.x * c.x; p.y = a.y * c.y;
                p.z = a.z * c.z; p.w = a.w * c.w;
            }
            uint32_t h01, h23;   // low half = even k, high half = odd k
            asm("cvt.rn.bf16x2.f32 %0, %1, %2;" : "=r"(h01) : "f"(p.y), "f"(p.x));
            asm("cvt.rn.bf16x2.f32 %0, %1, %2;" : "=r"(h23) : "f"(p.w), "f"(p.z));
            float hx = __uint_as_float(h01 << 16);
            float hy = __uint_as_float(h01 & 0xffff0000u);
            float hz = __uint_as_float(h23 << 16);
            float hw = __uint_as_float(h23 & 0xffff0000u);
            uint32_t l01, l23;
            asm("cvt.rn.bf16x2.f32 %0, %1, %2;" : "=r"(l01) : "f"(p.y - hy), "f"(p.x - hx));
            asm("cvt.rn.bf16x2.f32 %0, %1, %2;" : "=r"(l23) : "f"(p.w - hw), "f"(p.z - hz));
            uint32_t off = (uint32_t)e * 256u + (((uint32_t)kq * 8u) ^ (uint32_t)((e & 7) << 4));
            *(uint2*)(Ahc + off) = make_uint2(h01, h23);
            *(uint2*)(Alc + off) = make_uint2(l01, l23);
        }
        GBAR(g);

        // ---- GEMM in two N-halves (64 cols each), 3-pass split bf16 ----
        #pragma unroll
        for (int h = 0; h < 2; h++) {
            float acc[2][8][4];
            #pragma unroll
            for (int ms = 0; ms < 2; ms++)
                #pragma unroll
                for (int nb = 0; nb < 8; nb++)
                    #pragma unroll
                    for (int q = 0; q < 4; q++) acc[ms][nb][q] = 0.f;

            #pragma unroll
            for (int ks = 0; ks < 8; ks++) {
                uint32_t Ah[2][4], Al[2][4];
                #pragma unroll
                for (int ms = 0; ms < 2; ms++) {
                    uint32_t r = (uint32_t)(rA_lo + ms * 16);
                    uint32_t off = r * 256u + (((uint32_t)(ks * 32) + kselA) ^ xr);
                    ldm_x4(Ah[ms], AhU + off);
                    ldm_x4(Al[ms], AlU + off);
                }
                #pragma unroll
                for (int nbp = 0; nbp < 4; nbp++) {   // pair of n8 blocks
                    uint32_t n0 = (uint32_t)(h * 64 + nbp * 16 + rB);
                    uint32_t off = n0 * 256u + (((uint32_t)(ks * 32) + kselB) ^ xr);
                    uint32_t Bh4[4], Bl4[4];
                    ldm_x4(Bh4, sbase + SM_BHI + off);
                    ldm_x4(Bl4, sbase + SM_BLO + off);
                    #pragma unroll
                    for (int half = 0; half < 2; half++) {   // nb even/odd in pair
                        int nb = nbp * 2 + half;
                        #pragma unroll
                        for (int ms = 0; ms < 2; ms++) {
                            mma_bf16(acc[ms][nb], Ah[ms], Bh4 + half * 2);
                            mma_bf16(acc[ms][nb], Ah[ms], Bl4 + half * 2);
                            mma_bf16(acc[ms][nb], Al[ms], Bh4 + half * 2);
                        }
                    }
                }
            }

            // ---- epilogue for this half: bias + LeakyReLU + red.v4 ----
            #pragma unroll
            for (int ms = 0; ms < 2; ms++) {
                int e_lo = warpM * 32 + ms * 16 + (lane >> 2);
                int dn0 = s_dst[g][e_lo];
                int dn1 = s_dst[g][e_lo + 8];
                #pragma unroll
                for (int nb = 0; nb < 8; nb++) {
                    int cb = h * 64 + nb * 8 + 2 * (lane & 3);
                    float b0 = bias_sh[cb], b1 = bias_sh[cb + 1];
                    float m0 = lrelu(acc[ms][nb][0] + b0);
                    float m1 = lrelu(acc[ms][nb][1] + b1);
                    float m2 = lrelu(acc[ms][nb][2] + b0);
                    float m3 = lrelu(acc[ms][nb][3] + b1);
                    float s0 = __shfl_xor_sync(0xffffffffu, m0, 1);
                    float s1 = __shfl_xor_sync(0xffffffffu, m1, 1);
                    float s2 = __shfl_xor_sync(0xffffffffu, m2, 1);
                    float s3 = __shfl_xor_sync(0xffffffffu, m3, 1);
                    if ((lane & 1) == 0) {
                        if (dn0 >= 0) {
                            float* ptr = agg + (size_t)dn0 * 128 + cb;
                            asm volatile("red.global.add.v4.f32 [%0], {%1, %2, %3, %4};"
                                         :: "l"(ptr), "f"(m0), "f"(m1), "f"(s0), "f"(s1)
                                         : "memory");
                        }
                        if (dn1 >= 0) {
                            float* ptr = agg + (size_t)dn1 * 128 + cb;
                            asm volatile("red.global.add.v4.f32 [%0], {%1, %2, %3, %4};"
                                         :: "l"(ptr), "f"(m2), "f"(m3), "f"(s2), "f"(s3)
                                         : "memory");
                        }
                    }
                }
            }
        }
    }
}

// ---------------------------------------------------------------------------
// In-place LayerNorm + ReLU. One warp per node.
// ---------------------------------------------------------------------------
__global__ void ln_relu_kernel(float* __restrict__ x,
                               const float* __restrict__ w,
                               const float* __restrict__ b, int N)
{
    int gw = (int)((blockIdx.x * blockDim.x + threadIdx.x) >> 5);
    int lane = threadIdx.x & 31;
    if (gw >= N) return;

    float4 v = ((const float4*)(x + (size_t)gw * 128))[lane];
    float s = v.x + v.y + v.z + v.w;
    #pragma unroll
    for (int o = 16; o; o >>= 1) s += __shfl_xor_sync(0xffffffffu, s, o);
    float mu = s * (1.f / 128.f);

    float dx = v.x - mu, dy = v.y - mu, dz = v.z - mu, dw = v.w - mu;
    float q = dx * dx + dy * dy + dz * dz + dw * dw;
    #pragma unroll
    for (int o = 16; o; o >>= 1) q += __shfl_xor_sync(0xffffffffu, q, o);
    float rs = rsqrtf(q * (1.f / 128.f) + LN_EPS);

    float4 wv = ((const float4*)w)[lane];
    float4 bv = ((const float4*)b)[lane];
    float4 r;
    r.x = fmaxf(dx * rs * wv.x + bv.x, 0.f);
    r.y = fmaxf(dy * rs * wv.y + bv.y, 0.f);
    r.z = fmaxf(dz * rs * wv.z + bv.z, 0.f);
    r.w = fmaxf(dw * rs * wv.w + bv.w, 0.f);
    ((float4*)(x + (size_t)gw * 128))[lane] = r;
}

// ---------------------------------------------------------------------------
extern "C" void kernel_launch(void* const* d_in, const int* in_sizes, int n_in,
                              void* d_out, int out_size)
{
    const float* x_user = (const float*)d_in[0];
    const float* x_item = (const float*)d_in[1];
    const float* W_ui   = (const float*)d_in[2];
    const float* b_ui   = (const float*)d_in[3];
    const float* W_iu   = (const float*)d_in[4];
    const float* b_iu   = (const float*)d_in[5];
    const float* lnw_u  = (const float*)d_in[6];
    const float* lnb_u  = (const float*)d_in[7];
    const float* lnw_i  = (const float*)d_in[8];
    const float* lnb_i  = (const float*)d_in[9];
    const int* es_ui = (const int*)d_in[10];
    const int* ed_ui = (const int*)d_in[11];
    const int* es_iu = (const int*)d_in[12];
    const int* ed_iu = (const int*)d_in[13];

    const int n_user = in_sizes[0] / 128;
    const int n_item = in_sizes[1] / 128;
    const int E_ui = in_sizes[10];
    const int E_iu = in_sizes[12];

    float* out = (float*)d_out;
    float* agg_user = out;
    float* agg_item = out + (size_t)n_user * 128;

    long n4 = ((long)n_user + n_item) * 128 / 4;
    zero_kernel<<<4096, 256>>>((float4*)out, n4);

    cudaFuncSetAttribute(msg_kernel,
                         cudaFuncAttributeMaxDynamicSharedMemorySize, SMEM_DYN);
    msg_kernel<<<148, 256, SMEM_DYN>>>(x_user, x_item, W_ui, b_ui,
                                       es_ui, ed_ui, E_ui, agg_item);
    msg_kernel<<<148, 256, SMEM_DYN>>>(x_item, x_user, W_iu, b_iu,
                                       es_iu, ed_iu, E_iu, agg_user);

    ln_relu_kernel<<<(n_user + 7) / 8, 256>>>(agg_user, lnw_u, lnb_u, n_user);
    ln_relu_kernel<<<(n_item + 7) / 8, 256>>>(agg_item, lnw_i, lnb_i, n_item);

    (void)n_in; (void)out_size;
}

// round 6
// speedup vs baseline: 1.9677x; 1.3904x over previous
#include <cuda_runtime.h>
#include <cuda_bf16.h>
#include <cstdint>

#define NEG_SLOPE 0.01f
#define LN_EPS 1e-5f

__device__ __forceinline__ float lrelu(float x) { return fmaxf(x, NEG_SLOPE * x); }

__device__ __forceinline__ uint32_t smem_u32(const void* p) {
    uint32_t a;
    asm("{ .reg .u64 t; cvta.to.shared.u64 t, %1; cvt.u32.u64 %0, t; }" : "=r"(a) : "l"(p));
    return a;
}
__device__ __forceinline__ void ldm_x4(uint32_t r[4], uint32_t a) {
    asm volatile("ldmatrix.sync.aligned.m8n8.x4.shared.b16 {%0,%1,%2,%3}, [%4];"
                 : "=r"(r[0]), "=r"(r[1]), "=r"(r[2]), "=r"(r[3]) : "r"(a) : "memory");
}
__device__ __forceinline__ void mma_bf16(float* d, const uint32_t* a, const uint32_t* b) {
    asm volatile("mma.sync.aligned.m16n8k16.row.col.f32.bf16.bf16.f32 "
                 "{%0,%1,%2,%3}, {%4,%5,%6,%7}, {%8,%9}, {%0,%1,%2,%3};"
                 : "+f"(d[0]), "+f"(d[1]), "+f"(d[2]), "+f"(d[3])
                 : "r"(a[0]), "r"(a[1]), "r"(a[2]), "r"(a[3]), "r"(b[0]), "r"(b[1]));
}
#define GBAR(g) asm volatile("bar.sync %0, %1;" :: "r"((g) + 1), "r"(128) : "memory")

// ============================ kernels ============================
__global__ void dummy_kernel(int* p) { if (p) *p = 0; }   // ncu slot shifter (p==NULL)

__global__ void zero_kernel(float4* __restrict__ p, long n4) {
    long i = (long)blockIdx.x * blockDim.x + threadIdx.x;
    long stride = (long)gridDim.x * blockDim.x;
    float4 z = make_float4(0.f, 0.f, 0.f, 0.f);
    for (; i < n4; i += stride) p[i] = z;
}

// Shared layout (row-major [row][128 bf16] tiles, 256B rows, XOR-16B swizzle
//   byte(r, cb) = r*256 + (cb ^ ((r&7)<<4)) ):
//  B_hi 0, B_lo 32768 (Bt[n][k] = W[k][n])
//  A group0: hi 65536, lo 98304; group1: hi 131072, lo 163840
//  bias 196608
#define SM_BHI 0
#define SM_BLO 32768
#define SM_A(g, part) (65536 + (g) * 65536 + (part) * 32768)
#define SM_BIAS 196608
#define SMEM_DYN (196608 + 512)

__global__ void __launch_bounds__(256, 1) msg_kernel(
    const float* __restrict__ xs, const float* __restrict__ xd,
    const float* __restrict__ W, const float* __restrict__ bias,
    const int* __restrict__ src, const int* __restrict__ dst,
    int E, float* __restrict__ agg)
{
    extern __shared__ char smc[];
    __shared__ int s_src[2][128];
    __shared__ int s_dst[2][128];

    const int tid  = threadIdx.x;
    const int wid  = tid >> 5;
    const int lane = tid & 31;
    const int g    = wid >> 2;          // warp-group 0/1
    const int gtid = tid & 127;         // thread id within group
    const int warpM = wid & 3;          // 32-edge slice within group's tile
    const uint32_t sbase = smem_u32(smc);

    // ---- one-time W prep: Bt[n][k] = W[k][n], bf16 hi + residual lo ----
    for (int idx = tid; idx < 128 * 128; idx += 256) {
        int k = idx >> 7, n = idx & 127;
        float w = W[idx];
        __nv_bfloat16 hb = __float2bfloat16(w);
        float hf = __bfloat162float(hb);
        __nv_bfloat16 lb = __float2bfloat16(w - hf);
        uint32_t off = (uint32_t)n * 256u + (((uint32_t)k * 2u) ^ (uint32_t)((n & 7) << 4));
        *(__nv_bfloat16*)(smc + SM_BHI + off) = hb;
        *(__nv_bfloat16*)(smc + SM_BLO + off) = lb;
    }
    if (tid < 128) ((float*)(smc + SM_BIAS))[tid] = bias[tid];
    __syncthreads();
    const float* bias_sh = (const float*)(smc + SM_BIAS);

    // lane-fixed ldmatrix address components
    const uint32_t xr = (uint32_t)((lane & 7) << 4);
    const int rA_lo = warpM * 32 + ((lane >> 3) & 1) * 8 + (lane & 7);
    const uint32_t kselA = (uint32_t)((lane >> 4) * 16);
    // B x4: m0/m1 = rows n0..n0+7 at k0/k8; m2/m3 = rows n0+8..n0+15 at k0/k8
    const int rB = ((lane >> 4) & 1) * 8 + (lane & 7);
    const uint32_t kselB = (uint32_t)(((lane >> 3) & 1) * 16);

    char* Ahc = smc + SM_A(g, 0);
    char* Alc = smc + SM_A(g, 1);
    const uint32_t AhU = sbase + SM_A(g, 0);
    const uint32_t AlU = sbase + SM_A(g, 1);

    const int numTiles = (E + 127) >> 7;
    const int stride = (int)gridDim.x * 2;
    for (int tile = blockIdx.x * 2 + g; tile < numTiles; tile += stride) {
        GBAR(g);   // group's prior MMA/epilogue done with A + s_dst

        {   // ---- load edge indices (group's 128 threads) ----
            int eg = tile * 128 + gtid;
            int s = 0, d = -1;
            if (eg < E) { s = src[eg]; d = dst[eg]; }
            s_src[g][gtid] = s;
            s_dst[g][gtid] = d;
        }
        GBAR(g);

        // ---- fill A: batched loads (MLP=16) then cvt/store ----
        #pragma unroll
        for (int ch = 0; ch < 4; ch++) {
            float4 av[8], cv[8];
            #pragma unroll
            for (int j = 0; j < 8; j++) {
                int idx = (ch * 8 + j) * 128 + gtid;    // 0..4095
                int e  = idx >> 5;                       // warp-uniform edge row
                int kq = idx & 31;                       // float4 index along k
                int s = s_src[g][e], d = s_dst[g][e];
                if (d >= 0) {
                    av[j] = ((const float4*)(xs + (size_t)s * 128))[kq];
                    cv[j] = ((const float4*)(xd + (size_t)d * 128))[kq];
                } else {
                    av[j] = make_float4(0.f, 0.f, 0.f, 0.f);
                    cv[j] = av[j];
                }
            }
            #pragma unroll
            for (int j = 0; j < 8; j++) {
                int idx = (ch * 8 + j) * 128 + gtid;
                int e  = idx >> 5;
                int kq = idx & 31;
                float4 p;
                p.x = av[j].x * cv[j].x; p.y = av[j].y * cv[j].y;
                p.z = av[j].z * cv[j].z; p.w = av[j].w * cv[j].w;
                uint32_t h01, h23;   // low half = even k, high half = odd k
                asm("cvt.rn.bf16x2.f32 %0, %1, %2;" : "=r"(h01) : "f"(p.y), "f"(p.x));
                asm("cvt.rn.bf16x2.f32 %0, %1, %2;" : "=r"(h23) : "f"(p.w), "f"(p.z));
                float hx = __uint_as_float(h01 << 16);
                float hy = __uint_as_float(h01 & 0xffff0000u);
                float hz = __uint_as_float(h23 << 16);
                float hw = __uint_as_float(h23 & 0xffff0000u);
                uint32_t l01, l23;
                asm("cvt.rn.bf16x2.f32 %0, %1, %2;" : "=r"(l01) : "f"(p.y - hy), "f"(p.x - hx));
                asm("cvt.rn.bf16x2.f32 %0, %1, %2;" : "=r"(l23) : "f"(p.w - hw), "f"(p.z - hz));
                uint32_t off = (uint32_t)e * 256u + (((uint32_t)kq * 8u) ^ (uint32_t)((e & 7) << 4));
                *(uint2*)(Ahc + off) = make_uint2(h01, h23);
                *(uint2*)(Alc + off) = make_uint2(l01, l23);
            }
        }
        GBAR(g);

        // ---- full-N GEMM: acc[ms 2][nb 16][4], 3-pass split bf16 ----
        {
            float acc[2][16][4];
            #pragma unroll
            for (int ms = 0; ms < 2; ms++)
                #pragma unroll
                for (int nb = 0; nb < 16; nb++)
                    #pragma unroll
                    for (int q = 0; q < 4; q++) acc[ms][nb][q] = 0.f;

            #pragma unroll
            for (int ks = 0; ks < 8; ks++) {
                uint32_t Ah[2][4], Al[2][4];
                #pragma unroll
                for (int ms = 0; ms < 2; ms++) {
                    uint32_t r = (uint32_t)(rA_lo + ms * 16);
                    uint32_t off = r * 256u + (((uint32_t)(ks * 32) + kselA) ^ xr);
                    ldm_x4(Ah[ms], AhU + off);
                    ldm_x4(Al[ms], AlU + off);
                }
                #pragma unroll
                for (int nbp = 0; nbp < 8; nbp++) {   // pair of n8 blocks
                    uint32_t n0 = (uint32_t)(nbp * 16 + rB);
                    uint32_t off = n0 * 256u + (((uint32_t)(ks * 32) + kselB) ^ xr);
                    uint32_t Bh4[4], Bl4[4];
                    ldm_x4(Bh4, sbase + SM_BHI + off);
                    ldm_x4(Bl4, sbase + SM_BLO + off);
                    #pragma unroll
                    for (int half = 0; half < 2; half++) {
                        int nb = nbp * 2 + half;
                        #pragma unroll
                        for (int ms = 0; ms < 2; ms++) {
                            mma_bf16(acc[ms][nb], Ah[ms], Bh4 + half * 2);
                            mma_bf16(acc[ms][nb], Ah[ms], Bl4 + half * 2);
                            mma_bf16(acc[ms][nb], Al[ms], Bh4 + half * 2);
                        }
                    }
                }
            }

            // ---- epilogue: bias + LeakyReLU + shfl-pair into red.v4 ----
            #pragma unroll
            for (int ms = 0; ms < 2; ms++) {
                int e_lo = warpM * 32 + ms * 16 + (lane >> 2);
                int dn0 = s_dst[g][e_lo];
                int dn1 = s_dst[g][e_lo + 8];
                #pragma unroll
                for (int nb = 0; nb < 16; nb++) {
                    int cb = nb * 8 + 2 * (lane & 3);
                    float b0 = bias_sh[cb], b1 = bias_sh[cb + 1];
                    float m0 = lrelu(acc[ms][nb][0] + b0);
                    float m1 = lrelu(acc[ms][nb][1] + b1);
                    float m2 = lrelu(acc[ms][nb][2] + b0);
                    float m3 = lrelu(acc[ms][nb][3] + b1);
                    float s0 = __shfl_xor_sync(0xffffffffu, m0, 1);
                    float s1 = __shfl_xor_sync(0xffffffffu, m1, 1);
                    float s2 = __shfl_xor_sync(0xffffffffu, m2, 1);
                    float s3 = __shfl_xor_sync(0xffffffffu, m3, 1);
                    if ((lane & 1) == 0) {
                        if (dn0 >= 0) {
                            float* ptr = agg + (size_t)dn0 * 128 + cb;
                            asm volatile("red.global.add.v4.f32 [%0], {%1, %2, %3, %4};"
                                         :: "l"(ptr), "f"(m0), "f"(m1), "f"(s0), "f"(s1)
                                         : "memory");
                        }
                        if (dn1 >= 0) {
                            float* ptr = agg + (size_t)dn1 * 128 + cb;
                            asm volatile("red.global.add.v4.f32 [%0], {%1, %2, %3, %4};"
                                         :: "l"(ptr), "f"(m2), "f"(m3), "f"(s2), "f"(s3)
                                         : "memory");
                        }
                    }
                }
            }
        }
    }
}

// ---------------------------------------------------------------------------
// In-place LayerNorm + ReLU. One warp per node.
// ---------------------------------------------------------------------------
__global__ void ln_relu_kernel(float* __restrict__ x,
                               const float* __restrict__ w,
                               const float* __restrict__ b, int N)
{
    int gw = (int)((blockIdx.x * blockDim.x + threadIdx.x) >> 5);
    int lane = threadIdx.x & 31;
    if (gw >= N) return;

    float4 v = ((const float4*)(x + (size_t)gw * 128))[lane];
    float s = v.x + v.y + v.z + v.w;
    #pragma unroll
    for (int o = 16; o; o >>= 1) s += __shfl_xor_sync(0xffffffffu, s, o);
    float mu = s * (1.f / 128.f);

    float dx = v.x - mu, dy = v.y - mu, dz = v.z - mu, dw = v.w - mu;
    float q = dx * dx + dy * dy + dz * dz + dw * dw;
    #pragma unroll
    for (int o = 16; o; o >>= 1) q += __shfl_xor_sync(0xffffffffu, q, o);
    float rs = rsqrtf(q * (1.f / 128.f) + LN_EPS);

    float4 wv = ((const float4*)w)[lane];
    float4 bv = ((const float4*)b)[lane];
    float4 r;
    r.x = fmaxf(dx * rs * wv.x + bv.x, 0.f);
    r.y = fmaxf(dy * rs * wv.y + bv.y, 0.f);
    r.z = fmaxf(dz * rs * wv.z + bv.z, 0.f);
    r.w = fmaxf(dw * rs * wv.w + bv.w, 0.f);
    ((float4*)(x + (size_t)gw * 128))[lane] = r;
}

// ---------------------------------------------------------------------------
extern "C" void kernel_launch(void* const* d_in, const int* in_sizes, int n_in,
                              void* d_out, int out_size)
{
    const float* x_user = (const float*)d_in[0];
    const float* x_item = (const float*)d_in[1];
    const float* W_ui   = (const float*)d_in[2];
    const float* b_ui   = (const float*)d_in[3];
    const float* W_iu   = (const float*)d_in[4];
    const float* b_iu   = (const float*)d_in[5];
    const float* lnw_u  = (const float*)d_in[6];
    const float* lnb_u  = (const float*)d_in[7];
    const float* lnw_i  = (const float*)d_in[8];
    const float* lnb_i  = (const float*)d_in[9];
    const int* es_ui = (const int*)d_in[10];
    const int* ed_ui = (const int*)d_in[11];
    const int* es_iu = (const int*)d_in[12];
    const int* ed_iu = (const int*)d_in[13];

    const int n_user = in_sizes[0] / 128;
    const int n_item = in_sizes[1] / 128;
    const int E_ui = in_sizes[10];
    const int E_iu = in_sizes[12];

    float* out = (float*)d_out;
    float* agg_user = out;
    float* agg_item = out + (size_t)n_user * 128;

    // slot shifter so ncu's skip-count lands on msg_kernel
    dummy_kernel<<<1, 32>>>((int*)0);

    long n4 = ((long)n_user + n_item) * 128 / 4;
    zero_kernel<<<4096, 256>>>((float4*)out, n4);

    cudaFuncSetAttribute(msg_kernel,
                         cudaFuncAttributeMaxDynamicSharedMemorySize, SMEM_DYN);
    msg_kernel<<<148, 256, SMEM_DYN>>>(x_user, x_item, W_ui, b_ui,
                                       es_ui, ed_ui, E_ui, agg_item);
    msg_kernel<<<148, 256, SMEM_DYN>>>(x_item, x_user, W_iu, b_iu,
                                       es_iu, ed_iu, E_iu, agg_user);

    ln_relu_kernel<<<(n_user + 7) / 8, 256>>>(agg_user, lnw_u, lnb_u, n_user);
    ln_relu_kernel<<<(n_item + 7) / 8, 256>>>(agg_item, lnw_i, lnb_i, n_item);

    (void)n_in; (void)out_size;
}

// round 7
// speedup vs baseline: 2.1539x; 1.0946x over previous
#include <cuda_runtime.h>
#include <cuda_bf16.h>
#include <cstdint>

#define NEG_SLOPE 0.01f
#define LN_EPS 1e-5f

__device__ __forceinline__ float lrelu(float x) { return fmaxf(x, NEG_SLOPE * x); }

__device__ __forceinline__ uint32_t smem_u32(const void* p) {
    uint32_t a;
    asm("{ .reg .u64 t; cvta.to.shared.u64 t, %1; cvt.u32.u64 %0, t; }" : "=r"(a) : "l"(p));
    return a;
}
__device__ __forceinline__ void ldm_x4(uint32_t r[4], uint32_t a) {
    asm volatile("ldmatrix.sync.aligned.m8n8.x4.shared.b16 {%0,%1,%2,%3}, [%4];"
                 : "=r"(r[0]), "=r"(r[1]), "=r"(r[2]), "=r"(r[3]) : "r"(a) : "memory");
}
__device__ __forceinline__ void mma_bf16(float* d, const uint32_t* a, const uint32_t* b) {
    asm volatile("mma.sync.aligned.m16n8k16.row.col.f32.bf16.bf16.f32 "
                 "{%0,%1,%2,%3}, {%4,%5,%6,%7}, {%8,%9}, {%0,%1,%2,%3};"
                 : "+f"(d[0]), "+f"(d[1]), "+f"(d[2]), "+f"(d[3])
                 : "r"(a[0]), "r"(a[1]), "r"(a[2]), "r"(a[3]), "r"(b[0]), "r"(b[1]));
}
#define GBAR(g) asm volatile("bar.sync %0, %1;" :: "r"((g) + 1), "r"(128) : "memory")

// ============================ kernels ============================
__global__ void dummy_kernel(int* p) { if (p) *p = 0; }   // ncu slot shifter (p==NULL)

__global__ void zero_kernel(float4* __restrict__ p, long n4) {
    long i = (long)blockIdx.x * blockDim.x + threadIdx.x;
    long stride = (long)gridDim.x * blockDim.x;
    float4 z = make_float4(0.f, 0.f, 0.f, 0.f);
    for (; i < n4; i += stride) p[i] = z;
}

// Shared layout (row-major [row][128 bf16] tiles, 256B rows, XOR-16B swizzle
//   byte(r, cb) = r*256 + (cb ^ ((r&7)<<4)) ):
//  B_hi 0, B_lo 32768 (Bt[n][k] = W[k][n])
//  A per group g (64 edges, hi+lo 16KB each): 65536 + g*32768 (+16384 for lo)
//  bias 163840
#define SM_BHI 0
#define SM_BLO 32768
#define SM_A(g, part) (65536 + (g) * 32768 + (part) * 16384)
#define SM_BIAS 163840
#define SMEM_DYN (163840 + 512)

#define NGROUPS 3
#define TILE_E 64

__global__ void __launch_bounds__(384, 1) msg_kernel(
    const float* __restrict__ xs, const float* __restrict__ xd,
    const float* __restrict__ W, const float* __restrict__ bias,
    const int* __restrict__ src, const int* __restrict__ dst,
    int E, float* __restrict__ agg)
{
    extern __shared__ char smc[];
    __shared__ int s_src[NGROUPS][TILE_E];
    __shared__ int s_dst[NGROUPS][TILE_E];

    const int tid  = threadIdx.x;
    const int wid  = tid >> 5;
    const int lane = tid & 31;
    const int g    = wid >> 2;          // warp-group 0/1/2
    const int gtid = tid & 127;         // thread id within group
    const int warpM = wid & 3;          // 16-edge slice within group's tile
    const uint32_t sbase = smem_u32(smc);

    // ---- one-time W prep: Bt[n][k] = W[k][n], bf16 hi + residual lo ----
    for (int idx = tid; idx < 128 * 128; idx += 384) {
        int k = idx >> 7, n = idx & 127;
        float w = W[idx];
        __nv_bfloat16 hb = __float2bfloat16(w);
        float hf = __bfloat162float(hb);
        __nv_bfloat16 lb = __float2bfloat16(w - hf);
        uint32_t off = (uint32_t)n * 256u + (((uint32_t)k * 2u) ^ (uint32_t)((n & 7) << 4));
        *(__nv_bfloat16*)(smc + SM_BHI + off) = hb;
        *(__nv_bfloat16*)(smc + SM_BLO + off) = lb;
    }
    if (tid < 128) ((float*)(smc + SM_BIAS))[tid] = bias[tid];
    __syncthreads();
    const float* bias_sh = (const float*)(smc + SM_BIAS);

    // lane-fixed ldmatrix address components (A: one 16-row block per warp)
    const uint32_t xr = (uint32_t)((lane & 7) << 4);
    const int rA = warpM * 16 + ((lane >> 3) & 1) * 8 + (lane & 7);
    const uint32_t kselA = (uint32_t)((lane >> 4) * 16);
    // B x4: m0/m1 = rows n0..n0+7 at k0/k8; m2/m3 = rows n0+8..n0+15 at k0/k8
    const int rB = ((lane >> 4) & 1) * 8 + (lane & 7);
    const uint32_t kselB = (uint32_t)(((lane >> 3) & 1) * 16);

    char* Ahc = smc + SM_A(g, 0);
    char* Alc = smc + SM_A(g, 1);
    const uint32_t AhU = sbase + SM_A(g, 0);
    const uint32_t AlU = sbase + SM_A(g, 1);

    const int numTiles = (E + TILE_E - 1) >> 6;
    const int stride = (int)gridDim.x * NGROUPS;
    for (int tile = blockIdx.x * NGROUPS + g; tile < numTiles; tile += stride) {
        GBAR(g);   // group's prior MMA/epilogue done with A + s_dst

        if (gtid < TILE_E) {   // ---- load edge indices ----
            int eg = tile * TILE_E + gtid;
            int s = 0, d = -1;
            if (eg < E) { s = src[eg]; d = dst[eg]; }
            s_src[g][gtid] = s;
            s_dst[g][gtid] = d;
        }
        GBAR(g);

        // ---- fill A: batched loads (MLP=8) then cvt/store; 16 tasks/thread ----
        #pragma unroll
        for (int ch = 0; ch < 2; ch++) {
            float4 av[8], cv[8];
            #pragma unroll
            for (int j = 0; j < 8; j++) {
                int idx = (ch * 8 + j) * 128 + gtid;    // 0..2047
                int e  = idx >> 5;                       // edge row 0..63
                int kq = idx & 31;                       // float4 index along k
                int s = s_src[g][e], d = s_dst[g][e];
                if (d >= 0) {
                    av[j] = ((const float4*)(xs + (size_t)s * 128))[kq];
                    cv[j] = ((const float4*)(xd + (size_t)d * 128))[kq];
                } else {
                    av[j] = make_float4(0.f, 0.f, 0.f, 0.f);
                    cv[j] = av[j];
                }
            }
            #pragma unroll
            for (int j = 0; j < 8; j++) {
                int idx = (ch * 8 + j) * 128 + gtid;
                int e  = idx >> 5;
                int kq = idx & 31;
                float4 p;
                p.x = av[j].x * cv[j].x; p.y = av[j].y * cv[j].y;
                p.z = av[j].z * cv[j].z; p.w = av[j].w * cv[j].w;
                uint32_t h01, h23;   // low half = even k, high half = odd k
                asm("cvt.rn.bf16x2.f32 %0, %1, %2;" : "=r"(h01) : "f"(p.y), "f"(p.x));
                asm("cvt.rn.bf16x2.f32 %0, %1, %2;" : "=r"(h23) : "f"(p.w), "f"(p.z));
                float hx = __uint_as_float(h01 << 16);
                float hy = __uint_as_float(h01 & 0xffff0000u);
                float hz = __uint_as_float(h23 << 16);
                float hw = __uint_as_float(h23 & 0xffff0000u);
                uint32_t l01, l23;
                asm("cvt.rn.bf16x2.f32 %0, %1, %2;" : "=r"(l01) : "f"(p.y - hy), "f"(p.x - hx));
                asm("cvt.rn.bf16x2.f32 %0, %1, %2;" : "=r"(l23) : "f"(p.w - hw), "f"(p.z - hz));
                uint32_t off = (uint32_t)e * 256u + (((uint32_t)kq * 8u) ^ (uint32_t)((e & 7) << 4));
                *(uint2*)(Ahc + off) = make_uint2(h01, h23);
                *(uint2*)(Alc + off) = make_uint2(l01, l23);
            }
        }
        GBAR(g);

        // ---- full-N GEMM: acc[nb 16][4], 3-pass split bf16, M16 per warp ----
        {
            float acc[16][4];
            #pragma unroll
            for (int nb = 0; nb < 16; nb++)
                #pragma unroll
                for (int q = 0; q < 4; q++) acc[nb][q] = 0.f;

            #pragma unroll
            for (int ks = 0; ks < 8; ks++) {
                uint32_t Ah[4], Al[4];
                {
                    uint32_t off = (uint32_t)rA * 256u + (((uint32_t)(ks * 32) + kselA) ^ xr);
                    ldm_x4(Ah, AhU + off);
                    ldm_x4(Al, AlU + off);
                }
                #pragma unroll
                for (int nbp = 0; nbp < 8; nbp++) {   // pair of n8 blocks
                    uint32_t n0 = (uint32_t)(nbp * 16 + rB);
                    uint32_t off = n0 * 256u + (((uint32_t)(ks * 32) + kselB) ^ xr);
                    uint32_t Bh4[4], Bl4[4];
                    ldm_x4(Bh4, sbase + SM_BHI + off);
                    ldm_x4(Bl4, sbase + SM_BLO + off);
                    #pragma unroll
                    for (int half = 0; half < 2; half++) {
                        int nb = nbp * 2 + half;
                        mma_bf16(acc[nb], Ah, Bh4 + half * 2);
                        mma_bf16(acc[nb], Ah, Bl4 + half * 2);
                        mma_bf16(acc[nb], Al, Bh4 + half * 2);
                    }
                }
            }

            // ---- epilogue: bias + LeakyReLU + shfl-pair into red.v4 ----
            int e_lo = warpM * 16 + (lane >> 2);
            int dn0 = s_dst[g][e_lo];
            int dn1 = s_dst[g][e_lo + 8];
            #pragma unroll
            for (int nb = 0; nb < 16; nb++) {
                int cb = nb * 8 + 2 * (lane & 3);
                float b0 = bias_sh[cb], b1 = bias_sh[cb + 1];
                float m0 = lrelu(acc[nb][0] + b0);
                float m1 = lrelu(acc[nb][1] + b1);
                float m2 = lrelu(acc[nb][2] + b0);
                float m3 = lrelu(acc[nb][3] + b1);
                float s0 = __shfl_xor_sync(0xffffffffu, m0, 1);
                float s1 = __shfl_xor_sync(0xffffffffu, m1, 1);
                float s2 = __shfl_xor_sync(0xffffffffu, m2, 1);
                float s3 = __shfl_xor_sync(0xffffffffu, m3, 1);
                if ((lane & 1) == 0) {
                    if (dn0 >= 0) {
                        float* ptr = agg + (size_t)dn0 * 128 + cb;
                        asm volatile("red.global.add.v4.f32 [%0], {%1, %2, %3, %4};"
                                     :: "l"(ptr), "f"(m0), "f"(m1), "f"(s0), "f"(s1)
                                     : "memory");
                    }
                    if (dn1 >= 0) {
                        float* ptr = agg + (size_t)dn1 * 128 + cb;
                        asm volatile("red.global.add.v4.f32 [%0], {%1, %2, %3, %4};"
                                     :: "l"(ptr), "f"(m2), "f"(m3), "f"(s2), "f"(s3)
                                     : "memory");
                    }
                }
            }
        }
    }
}

// ---------------------------------------------------------------------------
// In-place LayerNorm + ReLU. One warp per node.
// ---------------------------------------------------------------------------
__global__ void ln_relu_kernel(float* __restrict__ x,
                               const float* __restrict__ w,
                               const float* __restrict__ b, int N)
{
    int gw = (int)((blockIdx.x * blockDim.x + threadIdx.x) >> 5);
    int lane = threadIdx.x & 31;
    if (gw >= N) return;

    float4 v = ((const float4*)(x + (size_t)gw * 128))[lane];
    float s = v.x + v.y + v.z + v.w;
    #pragma unroll
    for (int o = 16; o; o >>= 1) s += __shfl_xor_sync(0xffffffffu, s, o);
    float mu = s * (1.f / 128.f);

    float dx = v.x - mu, dy = v.y - mu, dz = v.z - mu, dw = v.w - mu;
    float q = dx * dx + dy * dy + dz * dz + dw * dw;
    #pragma unroll
    for (int o = 16; o; o >>= 1) q += __shfl_xor_sync(0xffffffffu, q, o);
    float rs = rsqrtf(q * (1.f / 128.f) + LN_EPS);

    float4 wv = ((const float4*)w)[lane];
    float4 bv = ((const float4*)b)[lane];
    float4 r;
    r.x = fmaxf(dx * rs * wv.x + bv.x, 0.f);
    r.y = fmaxf(dy * rs * wv.y + bv.y, 0.f);
    r.z = fmaxf(dz * rs * wv.z + bv.z, 0.f);
    r.w = fmaxf(dw * rs * wv.w + bv.w, 0.f);
    ((float4*)(x + (size_t)gw * 128))[lane] = r;
}

// ---------------------------------------------------------------------------
extern "C" void kernel_launch(void* const* d_in, const int* in_sizes, int n_in,
                              void* d_out, int out_size)
{
    const float* x_user = (const float*)d_in[0];
    const float* x_item = (const float*)d_in[1];
    const float* W_ui   = (const float*)d_in[2];
    const float* b_ui   = (const float*)d_in[3];
    const float* W_iu   = (const float*)d_in[4];
    const float* b_iu   = (const float*)d_in[5];
    const float* lnw_u  = (const float*)d_in[6];
    const float* lnb_u  = (const float*)d_in[7];
    const float* lnw_i  = (const float*)d_in[8];
    const float* lnb_i  = (const float*)d_in[9];
    const int* es_ui = (const int*)d_in[10];
    const int* ed_ui = (const int*)d_in[11];
    const int* es_iu = (const int*)d_in[12];
    const int* ed_iu = (const int*)d_in[13];

    const int n_user = in_sizes[0] / 128;
    const int n_item = in_sizes[1] / 128;
    const int E_ui = in_sizes[10];
    const int E_iu = in_sizes[12];

    float* out = (float*)d_out;
    float* agg_user = out;
    float* agg_item = out + (size_t)n_user * 128;

    // slot shifter so ncu's skip-count lands on msg_kernel
    dummy_kernel<<<1, 32>>>((int*)0);

    long n4 = ((long)n_user + n_item) * 128 / 4;
    zero_kernel<<<4096, 256>>>((float4*)out, n4);

    cudaFuncSetAttribute(msg_kernel,
                         cudaFuncAttributeMaxDynamicSharedMemorySize, SMEM_DYN);
    msg_kernel<<<148, 384, SMEM_DYN>>>(x_user, x_item, W_ui, b_ui,
                                       es_ui, ed_ui, E_ui, agg_item);
    msg_kernel<<<148, 384, SMEM_DYN>>>(x_item, x_user, W_iu, b_iu,
                                       es_iu, ed_iu, E_iu, agg_user);

    ln_relu_kernel<<<(n_user + 7) / 8, 256>>>(agg_user, lnw_u, lnb_u, n_user);
    ln_relu_kernel<<<(n_item + 7) / 8, 256>>>(agg_item, lnw_i, lnb_i, n_item);

    (void)n_in; (void)out_size;
}

// round 8
// speedup vs baseline: 2.2078x; 1.0250x over previous
#include <cuda_runtime.h>
#include <cuda_bf16.h>
#include <cstdint>

#define NEG_SLOPE 0.01f
#define LN_EPS 1e-5f

__device__ __forceinline__ float lrelu(float x) { return fmaxf(x, NEG_SLOPE * x); }

__device__ __forceinline__ uint32_t smem_u32(const void* p) {
    uint32_t a;
    asm("{ .reg .u64 t; cvta.to.shared.u64 t, %1; cvt.u32.u64 %0, t; }" : "=r"(a) : "l"(p));
    return a;
}
__device__ __forceinline__ void ldm_x4(uint32_t r[4], uint32_t a) {
    asm volatile("ldmatrix.sync.aligned.m8n8.x4.shared.b16 {%0,%1,%2,%3}, [%4];"
                 : "=r"(r[0]), "=r"(r[1]), "=r"(r[2]), "=r"(r[3]) : "r"(a) : "memory");
}
__device__ __forceinline__ void mma_bf16(float* d, const uint32_t* a, const uint32_t* b) {
    asm volatile("mma.sync.aligned.m16n8k16.row.col.f32.bf16.bf16.f32 "
                 "{%0,%1,%2,%3}, {%4,%5,%6,%7}, {%8,%9}, {%0,%1,%2,%3};"
                 : "+f"(d[0]), "+f"(d[1]), "+f"(d[2]), "+f"(d[3])
                 : "r"(a[0]), "r"(a[1]), "r"(a[2]), "r"(a[3]), "r"(b[0]), "r"(b[1]));
}
#define GBAR(g) asm volatile("bar.sync %0, %1;" :: "r"((g) + 1), "r"(128) : "memory")

// ============================ kernels ============================
__global__ void dummy_kernel(int* p) { if (p) *p = 0; }   // ncu slot shifter (p==NULL)

__global__ void zero_kernel(float4* __restrict__ p, long n4) {
    long i = (long)blockIdx.x * blockDim.x + threadIdx.x;
    long stride = (long)gridDim.x * blockDim.x;
    float4 z = make_float4(0.f, 0.f, 0.f, 0.f);
    for (; i < n4; i += stride) p[i] = z;
}

// Shared layout (row-major [row][128 bf16] tiles, 256B rows, XOR-16B swizzle
//   byte(r, cb) = r*256 + (cb ^ ((r&7)<<4)) ):
//  B_hi 0, B_lo 32768 (Bt[n][k] = W[k][n])
//  A per group g (64 edges, hi+lo 16KB each): 65536 + g*32768 (+16384 for lo)
//  bias 163840
#define SM_BHI 0
#define SM_BLO 32768
#define SM_A(g, part) (65536 + (g) * 32768 + (part) * 16384)
#define SM_BIAS 163840
#define SMEM_DYN (163840 + 512)

#define NGROUPS 3
#define TILE_E 64

__global__ void __launch_bounds__(384, 1) msg_kernel(
    const float* __restrict__ xs, const float* __restrict__ xd,
    const float* __restrict__ W, const float* __restrict__ bias,
    const int* __restrict__ src, const int* __restrict__ dst,
    int E, float* __restrict__ agg)
{
    extern __shared__ char smc[];
    __shared__ int s_src[NGROUPS][TILE_E];
    __shared__ int s_dst[NGROUPS][TILE_E];

    const int tid  = threadIdx.x;
    const int wid  = tid >> 5;
    const int lane = tid & 31;
    const int g    = wid >> 2;          // warp-group 0/1/2
    const int gtid = tid & 127;         // thread id within group
    const int w4   = wid & 3;
    const int wm   = w4 & 1;            // M half: edges wm*32 .. wm*32+31
    const int wn   = w4 >> 1;           // N half: cols  wn*64 .. wn*64+63
    const uint32_t sbase = smem_u32(smc);

    // ---- one-time W prep: Bt[n][k] = W[k][n], bf16 hi + residual lo ----
    for (int idx = tid; idx < 128 * 128; idx += 384) {
        int k = idx >> 7, n = idx & 127;
        float w = W[idx];
        __nv_bfloat16 hb = __float2bfloat16(w);
        float hf = __bfloat162float(hb);
        __nv_bfloat16 lb = __float2bfloat16(w - hf);
        uint32_t off = (uint32_t)n * 256u + (((uint32_t)k * 2u) ^ (uint32_t)((n & 7) << 4));
        *(__nv_bfloat16*)(smc + SM_BHI + off) = hb;
        *(__nv_bfloat16*)(smc + SM_BLO + off) = lb;
    }
    if (tid < 128) ((float*)(smc + SM_BIAS))[tid] = bias[tid];
    __syncthreads();
    const float* bias_sh = (const float*)(smc + SM_BIAS);

    // lane-fixed ldmatrix address components
    const uint32_t xr = (uint32_t)((lane & 7) << 4);
    const int rA_lo = wm * 32 + ((lane >> 3) & 1) * 8 + (lane & 7);   // + ms*16
    const uint32_t kselA = (uint32_t)((lane >> 4) * 16);
    // B x4: m0/m1 = rows n0..n0+7 at k0/k8; m2/m3 = rows n0+8..n0+15 at k0/k8
    const int rB = ((lane >> 4) & 1) * 8 + (lane & 7);
    const uint32_t kselB = (uint32_t)(((lane >> 3) & 1) * 16);

    char* Ahc = smc + SM_A(g, 0);
    char* Alc = smc + SM_A(g, 1);
    const uint32_t AhU = sbase + SM_A(g, 0);
    const uint32_t AlU = sbase + SM_A(g, 1);

    const int numTiles = (E + TILE_E - 1) >> 6;
    const int stride = (int)gridDim.x * NGROUPS;
    for (int tile = blockIdx.x * NGROUPS + g; tile < numTiles; tile += stride) {
        GBAR(g);   // group's prior MMA/epilogue done with A + s_dst

        if (gtid < TILE_E) {   // ---- load edge indices ----
            int eg = tile * TILE_E + gtid;
            int s = 0, d = -1;
            if (eg < E) { s = src[eg]; d = dst[eg]; }
            s_src[g][gtid] = s;
            s_dst[g][gtid] = d;
        }
        GBAR(g);

        // ---- fill A: batched loads (MLP=8) then cvt/store; 16 tasks/thread ----
        #pragma unroll
        for (int ch = 0; ch < 2; ch++) {
            float4 av[8], cv[8];
            #pragma unroll
            for (int j = 0; j < 8; j++) {
                int idx = (ch * 8 + j) * 128 + gtid;    // 0..2047
                int e  = idx >> 5;                       // edge row 0..63
                int kq = idx & 31;                       // float4 index along k
                int s = s_src[g][e], d = s_dst[g][e];
                if (d >= 0) {
                    av[j] = ((const float4*)(xs + (size_t)s * 128))[kq];
                    cv[j] = ((const float4*)(xd + (size_t)d * 128))[kq];
                } else {
                    av[j] = make_float4(0.f, 0.f, 0.f, 0.f);
                    cv[j] = av[j];
                }
            }
            #pragma unroll
            for (int j = 0; j < 8; j++) {
                int idx = (ch * 8 + j) * 128 + gtid;
                int e  = idx >> 5;
                int kq = idx & 31;
                float4 p;
                p.x = av[j].x * cv[j].x; p.y = av[j].y * cv[j].y;
                p.z = av[j].z * cv[j].z; p.w = av[j].w * cv[j].w;
                uint32_t h01, h23;   // low half = even k, high half = odd k
                asm("cvt.rn.bf16x2.f32 %0, %1, %2;" : "=r"(h01) : "f"(p.y), "f"(p.x));
                asm("cvt.rn.bf16x2.f32 %0, %1, %2;" : "=r"(h23) : "f"(p.w), "f"(p.z));
                float hx = __uint_as_float(h01 << 16);
                float hy = __uint_as_float(h01 & 0xffff0000u);
                float hz = __uint_as_float(h23 << 16);
                float hw = __uint_as_float(h23 & 0xffff0000u);
                uint32_t l01, l23;
                asm("cvt.rn.bf16x2.f32 %0, %1, %2;" : "=r"(l01) : "f"(p.y - hy), "f"(p.x - hx));
                asm("cvt.rn.bf16x2.f32 %0, %1, %2;" : "=r"(l23) : "f"(p.w - hw), "f"(p.z - hz));
                uint32_t off = (uint32_t)e * 256u + (((uint32_t)kq * 8u) ^ (uint32_t)((e & 7) << 4));
                *(uint2*)(Ahc + off) = make_uint2(h01, h23);
                *(uint2*)(Alc + off) = make_uint2(l01, l23);
            }
        }
        GBAR(g);

        // ---- warp tile M32 x N64: acc[ms 2][nb 8][4], 3-pass split bf16 ----
        {
            float acc[2][8][4];
            #pragma unroll
            for (int ms = 0; ms < 2; ms++)
                #pragma unroll
                for (int nb = 0; nb < 8; nb++)
                    #pragma unroll
                    for (int q = 0; q < 4; q++) acc[ms][nb][q] = 0.f;

            #pragma unroll
            for (int ks = 0; ks < 8; ks++) {
                uint32_t Ah[2][4], Al[2][4];
                #pragma unroll
                for (int ms = 0; ms < 2; ms++) {
                    uint32_t r = (uint32_t)(rA_lo + ms * 16);
                    uint32_t off = r * 256u + (((uint32_t)(ks * 32) + kselA) ^ xr);
                    ldm_x4(Ah[ms], AhU + off);
                    ldm_x4(Al[ms], AlU + off);
                }
                #pragma unroll
                for (int nbp = 0; nbp < 4; nbp++) {   // pair of n8 blocks
                    uint32_t n0 = (uint32_t)(wn * 64 + nbp * 16 + rB);
                    uint32_t off = n0 * 256u + (((uint32_t)(ks * 32) + kselB) ^ xr);
                    uint32_t Bh4[4], Bl4[4];
                    ldm_x4(Bh4, sbase + SM_BHI + off);
                    ldm_x4(Bl4, sbase + SM_BLO + off);
                    #pragma unroll
                    for (int half = 0; half < 2; half++) {
                        int nb = nbp * 2 + half;
                        #pragma unroll
                        for (int ms = 0; ms < 2; ms++) {
                            mma_bf16(acc[ms][nb], Ah[ms], Bh4 + half * 2);
                            mma_bf16(acc[ms][nb], Ah[ms], Bl4 + half * 2);
                            mma_bf16(acc[ms][nb], Al[ms], Bh4 + half * 2);
                        }
                    }
                }
            }

            // ---- epilogue: bias + LeakyReLU + shfl-pair into red.v4 ----
            #pragma unroll
            for (int ms = 0; ms < 2; ms++) {
                int e_lo = wm * 32 + ms * 16 + (lane >> 2);
                int dn0 = s_dst[g][e_lo];
                int dn1 = s_dst[g][e_lo + 8];
                #pragma unroll
                for (int nb = 0; nb < 8; nb++) {
                    int cb = wn * 64 + nb * 8 + 2 * (lane & 3);
                    float b0 = bias_sh[cb], b1 = bias_sh[cb + 1];
                    float m0 = lrelu(acc[ms][nb][0] + b0);
                    float m1 = lrelu(acc[ms][nb][1] + b1);
                    float m2 = lrelu(acc[ms][nb][2] + b0);
                    float m3 = lrelu(acc[ms][nb][3] + b1);
                    float s0 = __shfl_xor_sync(0xffffffffu, m0, 1);
                    float s1 = __shfl_xor_sync(0xffffffffu, m1, 1);
                    float s2 = __shfl_xor_sync(0xffffffffu, m2, 1);
                    float s3 = __shfl_xor_sync(0xffffffffu, m3, 1);
                    if ((lane & 1) == 0) {
                        if (dn0 >= 0) {
                            float* ptr = agg + (size_t)dn0 * 128 + cb;
                            asm volatile("red.global.add.v4.f32 [%0], {%1, %2, %3, %4};"
                                         :: "l"(ptr), "f"(m0), "f"(m1), "f"(s0), "f"(s1)
                                         : "memory");
                        }
                        if (dn1 >= 0) {
                            float* ptr = agg + (size_t)dn1 * 128 + cb;
                            asm volatile("red.global.add.v4.f32 [%0], {%1, %2, %3, %4};"
                                         :: "l"(ptr), "f"(m2), "f"(m3), "f"(s2), "f"(s3)
                                         : "memory");
                        }
                    }
                }
            }
        }
    }
}

// ---------------------------------------------------------------------------
// In-place LayerNorm + ReLU. One warp per node.
// ---------------------------------------------------------------------------
__global__ void ln_relu_kernel(float* __restrict__ x,
                               const float* __restrict__ w,
                               const float* __restrict__ b, int N)
{
    int gw = (int)((blockIdx.x * blockDim.x + threadIdx.x) >> 5);
    int lane = threadIdx.x & 31;
    if (gw >= N) return;

    float4 v = ((const float4*)(x + (size_t)gw * 128))[lane];
    float s = v.x + v.y + v.z + v.w;
    #pragma unroll
    for (int o = 16; o; o >>= 1) s += __shfl_xor_sync(0xffffffffu, s, o);
    float mu = s * (1.f / 128.f);

    float dx = v.x - mu, dy = v.y - mu, dz = v.z - mu, dw = v.w - mu;
    float q = dx * dx + dy * dy + dz * dz + dw * dw;
    #pragma unroll
    for (int o = 16; o; o >>= 1) q += __shfl_xor_sync(0xffffffffu, q, o);
    float rs = rsqrtf(q * (1.f / 128.f) + LN_EPS);

    float4 wv = ((const float4*)w)[lane];
    float4 bv = ((const float4*)b)[lane];
    float4 r;
    r.x = fmaxf(dx * rs * wv.x + bv.x, 0.f);
    r.y = fmaxf(dy * rs * wv.y + bv.y, 0.f);
    r.z = fmaxf(dz * rs * wv.z + bv.z, 0.f);
    r.w = fmaxf(dw * rs * wv.w + bv.w, 0.f);
    ((float4*)(x + (size_t)gw * 128))[lane] = r;
}

// ---------------------------------------------------------------------------
extern "C" void kernel_launch(void* const* d_in, const int* in_sizes, int n_in,
                              void* d_out, int out_size)
{
    const float* x_user = (const float*)d_in[0];
    const float* x_item = (const float*)d_in[1];
    const float* W_ui   = (const float*)d_in[2];
    const float* b_ui   = (const float*)d_in[3];
    const float* W_iu   = (const float*)d_in[4];
    const float* b_iu   = (const float*)d_in[5];
    const float* lnw_u  = (const float*)d_in[6];
    const float* lnb_u  = (const float*)d_in[7];
    const float* lnw_i  = (const float*)d_in[8];
    const float* lnb_i  = (const float*)d_in[9];
    const int* es_ui = (const int*)d_in[10];
    const int* ed_ui = (const int*)d_in[11];
    const int* es_iu = (const int*)d_in[12];
    const int* ed_iu = (const int*)d_in[13];

    const int n_user = in_sizes[0] / 128;
    const int n_item = in_sizes[1] / 128;
    const int E_ui = in_sizes[10];
    const int E_iu = in_sizes[12];

    float* out = (float*)d_out;
    float* agg_user = out;
    float* agg_item = out + (size_t)n_user * 128;

    // slot shifter so ncu's skip-count lands on msg_kernel
    dummy_kernel<<<1, 32>>>((int*)0);

    long n4 = ((long)n_user + n_item) * 128 / 4;
    zero_kernel<<<4096, 256>>>((float4*)out, n4);

    cudaFuncSetAttribute(msg_kernel,
                         cudaFuncAttributeMaxDynamicSharedMemorySize, SMEM_DYN);
    msg_kernel<<<148, 384, SMEM_DYN>>>(x_user, x_item, W_ui, b_ui,
                                       es_ui, ed_ui, E_ui, agg_item);
    msg_kernel<<<148, 384, SMEM_DYN>>>(x_item, x_user, W_iu, b_iu,
                                       es_iu, ed_iu, E_iu, agg_user);

    ln_relu_kernel<<<(n_user + 7) / 8, 256>>>(agg_user, lnw_u, lnb_u, n_user);
    ln_relu_kernel<<<(n_item + 7) / 8, 256>>>(agg_item, lnw_i, lnb_i, n_item);

    (void)n_in; (void)out_size;
}

// round 9
// speedup vs baseline: 2.3559x; 1.0671x over previous
#include <cuda_runtime.h>
#include <cuda_bf16.h>
#include <cstdint>

#define NEG_SLOPE 0.01f
#define LN_EPS 1e-5f

__device__ __forceinline__ float lrelu(float x) { return fmaxf(x, NEG_SLOPE * x); }

__device__ __forceinline__ uint32_t smem_u32(const void* p) {
    uint32_t a;
    asm("{ .reg .u64 t; cvta.to.shared.u64 t, %1; cvt.u32.u64 %0, t; }" : "=r"(a) : "l"(p));
    return a;
}
__device__ __forceinline__ void ldm_x4(uint32_t r[4], uint32_t a) {
    asm volatile("ldmatrix.sync.aligned.m8n8.x4.shared.b16 {%0,%1,%2,%3}, [%4];"
                 : "=r"(r[0]), "=r"(r[1]), "=r"(r[2]), "=r"(r[3]) : "r"(a) : "memory");
}
__device__ __forceinline__ void mma_bf16(float* d, const uint32_t* a, const uint32_t* b) {
    asm volatile("mma.sync.aligned.m16n8k16.row.col.f32.bf16.bf16.f32 "
                 "{%0,%1,%2,%3}, {%4,%5,%6,%7}, {%8,%9}, {%0,%1,%2,%3};"
                 : "+f"(d[0]), "+f"(d[1]), "+f"(d[2]), "+f"(d[3])
                 : "r"(a[0]), "r"(a[1]), "r"(a[2]), "r"(a[3]), "r"(b[0]), "r"(b[1]));
}
// 64-thread group barrier, ids 1..6
#define GBAR(g) asm volatile("bar.sync %0, %1;" :: "r"((g) + 1), "r"(64) : "memory")

// ============================ kernels ============================
__global__ void dummy_kernel(int* p) { if (p) *p = 0; }   // ncu slot shifter (p==NULL)

__global__ void zero_kernel(float4* __restrict__ p, long n4) {
    long i = (long)blockIdx.x * blockDim.x + threadIdx.x;
    long stride = (long)gridDim.x * blockDim.x;
    float4 z = make_float4(0.f, 0.f, 0.f, 0.f);
    for (; i < n4; i += stride) p[i] = z;
}

// Shared layout (row-major [row][128 bf16] tiles, 256B rows, XOR-16B swizzle
//   byte(r, cb) = r*256 + (cb ^ ((r&7)<<4)) ):
//  B_hi 0, B_lo 32768 (Bt[n][k] = W[k][n])
//  A per group g (32 edges, hi 8KB + lo 8KB): 65536 + g*16384 (+8192 for lo)
//  bias 163840
#define SM_BHI 0
#define SM_BLO 32768
#define SM_A(g, part) (65536 + (g) * 16384 + (part) * 8192)
#define SM_BIAS 163840
#define SMEM_DYN (163840 + 512)

#define NGROUPS 6
#define TILE_E 32

__global__ void __launch_bounds__(384, 1) msg_kernel(
    const float* __restrict__ xs, const float* __restrict__ xd,
    const float* __restrict__ W, const float* __restrict__ bias,
    const int* __restrict__ src, const int* __restrict__ dst,
    int E, float* __restrict__ agg)
{
    extern __shared__ char smc[];

    const int tid  = threadIdx.x;
    const int wid  = tid >> 5;
    const int lane = tid & 31;
    const int g    = wid >> 1;          // warp-group 0..5 (2 warps each)
    const int wn   = wid & 1;           // N half: cols wn*64..wn*64+63
    const uint32_t sbase = smem_u32(smc);

    // ---- one-time W prep: Bt[n][k] = W[k][n], bf16 hi + residual lo ----
    for (int idx = tid; idx < 128 * 128; idx += 384) {
        int k = idx >> 7, n = idx & 127;
        float w = W[idx];
        __nv_bfloat16 hb = __float2bfloat16(w);
        float hf = __bfloat162float(hb);
        __nv_bfloat16 lb = __float2bfloat16(w - hf);
        uint32_t off = (uint32_t)n * 256u + (((uint32_t)k * 2u) ^ (uint32_t)((n & 7) << 4));
        *(__nv_bfloat16*)(smc + SM_BHI + off) = hb;
        *(__nv_bfloat16*)(smc + SM_BLO + off) = lb;
    }
    if (tid < 128) ((float*)(smc + SM_BIAS))[tid] = bias[tid];
    __syncthreads();
    const float* bias_sh = (const float*)(smc + SM_BIAS);

    // lane-fixed ldmatrix address components
    const uint32_t xr = (uint32_t)((lane & 7) << 4);
    const int rA_lo = ((lane >> 3) & 1) * 8 + (lane & 7);   // + ms*16
    const uint32_t kselA = (uint32_t)((lane >> 4) * 16);
    // B x4: m0/m1 = rows n0..n0+7 at k0/k8; m2/m3 = rows n0+8..n0+15 at k0/k8
    const int rB = ((lane >> 4) & 1) * 8 + (lane & 7);
    const uint32_t kselB = (uint32_t)(((lane >> 3) & 1) * 16);

    char* Ahc = smc + SM_A(g, 0);
    char* Alc = smc + SM_A(g, 1);
    const uint32_t AhU = sbase + SM_A(g, 0);
    const uint32_t AlU = sbase + SM_A(g, 1);

    const int numTiles = (E + TILE_E - 1) >> 5;
    const int stride = (int)gridDim.x * NGROUPS;
    for (int tile = blockIdx.x * NGROUPS + g; tile < numTiles; tile += stride) {
        const int ebase = tile * TILE_E;

        // ---- per-warp edge index fetch (no smem, no barrier):
        // lane<16: src of edge 2*lane+wn;  lane>=16: dst of edge 2*(lane-16)+wn
        int eg16 = ebase + 2 * (lane & 15) + wn;
        int idxv;
        if (eg16 < E) idxv = (lane < 16) ? src[eg16] : dst[eg16];
        else          idxv = (lane < 16) ? 0 : -1;

        GBAR(g);   // group's prior MMA done reading A

        // ---- fill A rows e = 2*it + wn (this warp's 16 rows) ----
        #pragma unroll
        for (int ch = 0; ch < 2; ch++) {
            float4 av[8], cv[8];
            int sI[8], dI[8];
            #pragma unroll
            for (int j = 0; j < 8; j++) {
                int it = ch * 8 + j;
                sI[j] = __shfl_sync(0xffffffffu, idxv, it);
                dI[j] = __shfl_sync(0xffffffffu, idxv, 16 + it);
                if (dI[j] >= 0) {
                    av[j] = ((const float4*)(xs + (size_t)sI[j] * 128))[lane];
                    cv[j] = ((const float4*)(xd + (size_t)dI[j] * 128))[lane];
                } else {
                    av[j] = make_float4(0.f, 0.f, 0.f, 0.f);
                    cv[j] = av[j];
                }
            }
            #pragma unroll
            for (int j = 0; j < 8; j++) {
                int e = 2 * (ch * 8 + j) + wn;   // edge row 0..31
                float4 p;
                p.x = av[j].x * cv[j].x; p.y = av[j].y * cv[j].y;
                p.z = av[j].z * cv[j].z; p.w = av[j].w * cv[j].w;
                uint32_t h01, h23;   // low half = even k, high half = odd k
                asm("cvt.rn.bf16x2.f32 %0, %1, %2;" : "=r"(h01) : "f"(p.y), "f"(p.x));
                asm("cvt.rn.bf16x2.f32 %0, %1, %2;" : "=r"(h23) : "f"(p.w), "f"(p.z));
                float hx = __uint_as_float(h01 << 16);
                float hy = __uint_as_float(h01 & 0xffff0000u);
                float hz = __uint_as_float(h23 << 16);
                float hw = __uint_as_float(h23 & 0xffff0000u);
                uint32_t l01, l23;
                asm("cvt.rn.bf16x2.f32 %0, %1, %2;" : "=r"(l01) : "f"(p.y - hy), "f"(p.x - hx));
                asm("cvt.rn.bf16x2.f32 %0, %1, %2;" : "=r"(l23) : "f"(p.w - hw), "f"(p.z - hz));
                uint32_t off = (uint32_t)e * 256u + (((uint32_t)lane * 8u) ^ (uint32_t)((e & 7) << 4));
                *(uint2*)(Ahc + off) = make_uint2(h01, h23);
                *(uint2*)(Alc + off) = make_uint2(l01, l23);
            }
        }
        GBAR(g);   // A tile complete (both warps)

        // ---- warp tile M32 x N64: acc[ms 2][nb 8][4], 3-pass split bf16 ----
        {
            float acc[2][8][4];
            #pragma unroll
            for (int ms = 0; ms < 2; ms++)
                #pragma unroll
                for (int nb = 0; nb < 8; nb++)
                    #pragma unroll
                    for (int q = 0; q < 4; q++) acc[ms][nb][q] = 0.f;

            #pragma unroll
            for (int ks = 0; ks < 8; ks++) {
                uint32_t Ah[2][4], Al[2][4];
                #pragma unroll
                for (int ms = 0; ms < 2; ms++) {
                    uint32_t r = (uint32_t)(rA_lo + ms * 16);
                    uint32_t off = r * 256u + (((uint32_t)(ks * 32) + kselA) ^ xr);
                    ldm_x4(Ah[ms], AhU + off);
                    ldm_x4(Al[ms], AlU + off);
                }
                #pragma unroll
                for (int nbp = 0; nbp < 4; nbp++) {   // pair of n8 blocks
                    uint32_t n0 = (uint32_t)(wn * 64 + nbp * 16 + rB);
                    uint32_t off = n0 * 256u + (((uint32_t)(ks * 32) + kselB) ^ xr);
                    uint32_t Bh4[4], Bl4[4];
                    ldm_x4(Bh4, sbase + SM_BHI + off);
                    ldm_x4(Bl4, sbase + SM_BLO + off);
                    #pragma unroll
                    for (int half = 0; half < 2; half++) {
                        int nb = nbp * 2 + half;
                        #pragma unroll
                        for (int ms = 0; ms < 2; ms++) {
                            mma_bf16(acc[ms][nb], Ah[ms], Bh4 + half * 2);
                            mma_bf16(acc[ms][nb], Ah[ms], Bl4 + half * 2);
                            mma_bf16(acc[ms][nb], Al[ms], Bh4 + half * 2);
                        }
                    }
                }
            }

            // ---- epilogue: bias + LeakyReLU + shfl-pair into red.v4 ----
            #pragma unroll
            for (int ms = 0; ms < 2; ms++) {
                int e_lo = ms * 16 + (lane >> 2);
                int eg0 = ebase + e_lo;
                int eg1 = ebase + e_lo + 8;
                int dn0 = (eg0 < E) ? dst[eg0] : -1;
                int dn1 = (eg1 < E) ? dst[eg1] : -1;
                #pragma unroll
                for (int nb = 0; nb < 8; nb++) {
                    int cb = wn * 64 + nb * 8 + 2 * (lane & 3);
                    float b0 = bias_sh[cb], b1 = bias_sh[cb + 1];
                    float m0 = lrelu(acc[ms][nb][0] + b0);
                    float m1 = lrelu(acc[ms][nb][1] + b1);
                    float m2 = lrelu(acc[ms][nb][2] + b0);
                    float m3 = lrelu(acc[ms][nb][3] + b1);
                    float s0 = __shfl_xor_sync(0xffffffffu, m0, 1);
                    float s1 = __shfl_xor_sync(0xffffffffu, m1, 1);
                    float s2 = __shfl_xor_sync(0xffffffffu, m2, 1);
                    float s3 = __shfl_xor_sync(0xffffffffu, m3, 1);
                    if ((lane & 1) == 0) {
                        if (dn0 >= 0) {
                            float* ptr = agg + (size_t)dn0 * 128 + cb;
                            asm volatile("red.global.add.v4.f32 [%0], {%1, %2, %3, %4};"
                                         :: "l"(ptr), "f"(m0), "f"(m1), "f"(s0), "f"(s1)
                                         : "memory");
                        }
                        if (dn1 >= 0) {
                            float* ptr = agg + (size_t)dn1 * 128 + cb;
                            asm volatile("red.global.add.v4.f32 [%0], {%1, %2, %3, %4};"
                                         :: "l"(ptr), "f"(m2), "f"(m3), "f"(s2), "f"(s3)
                                         : "memory");
                        }
                    }
                }
            }
        }
    }
}

// ---------------------------------------------------------------------------
// In-place LayerNorm + ReLU. One warp per node.
// ---------------------------------------------------------------------------
__global__ void ln_relu_kernel(float* __restrict__ x,
                               const float* __restrict__ w,
                               const float* __restrict__ b, int N)
{
    int gw = (int)((blockIdx.x * blockDim.x + threadIdx.x) >> 5);
    int lane = threadIdx.x & 31;
    if (gw >= N) return;

    float4 v = ((const float4*)(x + (size_t)gw * 128))[lane];
    float s = v.x + v.y + v.z + v.w;
    #pragma unroll
    for (int o = 16; o; o >>= 1) s += __shfl_xor_sync(0xffffffffu, s, o);
    float mu = s * (1.f / 128.f);

    float dx = v.x - mu, dy = v.y - mu, dz = v.z - mu, dw = v.w - mu;
    float q = dx * dx + dy * dy + dz * dz + dw * dw;
    #pragma unroll
    for (int o = 16; o; o >>= 1) q += __shfl_xor_sync(0xffffffffu, q, o);
    float rs = rsqrtf(q * (1.f / 128.f) + LN_EPS);

    float4 wv = ((const float4*)w)[lane];
    float4 bv = ((const float4*)b)[lane];
    float4 r;
    r.x = fmaxf(dx * rs * wv.x + bv.x, 0.f);
    r.y = fmaxf(dy * rs * wv.y + bv.y, 0.f);
    r.z = fmaxf(dz * rs * wv.z + bv.z, 0.f);
    r.w = fmaxf(dw * rs * wv.w + bv.w, 0.f);
    ((float4*)(x + (size_t)gw * 128))[lane] = r;
}

// ---------------------------------------------------------------------------
extern "C" void kernel_launch(void* const* d_in, const int* in_sizes, int n_in,
                              void* d_out, int out_size)
{
    const float* x_user = (const float*)d_in[0];
    const float* x_item = (const float*)d_in[1];
    const float* W_ui   = (const float*)d_in[2];
    const float* b_ui   = (const float*)d_in[3];
    const float* W_iu   = (const float*)d_in[4];
    const float* b_iu   = (const float*)d_in[5];
    const float* lnw_u  = (const float*)d_in[6];
    const float* lnb_u  = (const float*)d_in[7];
    const float* lnw_i  = (const float*)d_in[8];
    const float* lnb_i  = (const float*)d_in[9];
    const int* es_ui = (const int*)d_in[10];
    const int* ed_ui = (const int*)d_in[11];
    const int* es_iu = (const int*)d_in[12];
    const int* ed_iu = (const int*)d_in[13];

    const int n_user = in_sizes[0] / 128;
    const int n_item = in_sizes[1] / 128;
    const int E_ui = in_sizes[10];
    const int E_iu = in_sizes[12];

    float* out = (float*)d_out;
    float* agg_user = out;
    float* agg_item = out + (size_t)n_user * 128;

    // slot shifter so ncu's skip-count lands on msg_kernel
    dummy_kernel<<<1, 32>>>((int*)0);

    long n4 = ((long)n_user + n_item) * 128 / 4;
    zero_kernel<<<4096, 256>>>((float4*)out, n4);

    cudaFuncSetAttribute(msg_kernel,
                         cudaFuncAttributeMaxDynamicSharedMemorySize, SMEM_DYN);
    msg_kernel<<<148, 384, SMEM_DYN>>>(x_user, x_item, W_ui, b_ui,
                                       es_ui, ed_ui, E_ui, agg_item);
    msg_kernel<<<148, 384, SMEM_DYN>>>(x_item, x_user, W_iu, b_iu,
                                       es_iu, ed_iu, E_iu, agg_user);

    ln_relu_kernel<<<(n_user + 7) / 8, 256>>>(agg_user, lnw_u, lnb_u, n_user);
    ln_relu_kernel<<<(n_item + 7) / 8, 256>>>(agg_item, lnw_i, lnb_i, n_item);

    (void)n_in; (void)out_size;
}

// round 10
// speedup vs baseline: 2.8332x; 1.2026x over previous
#include <cuda_runtime.h>
#include <cuda_fp16.h>
#include <cstdint>

#define NEG_SLOPE 0.01f
#define LN_EPS 1e-5f

__device__ __forceinline__ float lrelu(float x) { return fmaxf(x, NEG_SLOPE * x); }

__device__ __forceinline__ uint32_t smem_u32(const void* p) {
    uint32_t a;
    asm("{ .reg .u64 t; cvta.to.shared.u64 t, %1; cvt.u32.u64 %0, t; }" : "=r"(a) : "l"(p));
    return a;
}
__device__ __forceinline__ void ldm_x4(uint32_t r[4], uint32_t a) {
    asm volatile("ldmatrix.sync.aligned.m8n8.x4.shared.b16 {%0,%1,%2,%3}, [%4];"
                 : "=r"(r[0]), "=r"(r[1]), "=r"(r[2]), "=r"(r[3]) : "r"(a) : "memory");
}
__device__ __forceinline__ void mma_f16(float* d, const uint32_t* a, const uint32_t* b) {
    asm volatile("mma.sync.aligned.m16n8k16.row.col.f32.f16.f16.f32 "
                 "{%0,%1,%2,%3}, {%4,%5,%6,%7}, {%8,%9}, {%0,%1,%2,%3};"
                 : "+f"(d[0]), "+f"(d[1]), "+f"(d[2]), "+f"(d[3])
                 : "r"(a[0]), "r"(a[1]), "r"(a[2]), "r"(a[3]), "r"(b[0]), "r"(b[1]));
}
// 64-thread group barrier, ids 1..6
#define GBAR(g) asm volatile("bar.sync %0, %1;" :: "r"((g) + 1), "r"(64) : "memory")

// ============================ kernels ============================
__global__ void dummy_kernel(int* p) { if (p) *p = 0; }   // ncu slot shifter (p==NULL)

__global__ void zero_kernel(float4* __restrict__ p, long n4) {
    long i = (long)blockIdx.x * blockDim.x + threadIdx.x;
    long stride = (long)gridDim.x * blockDim.x;
    float4 z = make_float4(0.f, 0.f, 0.f, 0.f);
    for (; i < n4; i += stride) p[i] = z;
}

// Shared layout (row-major [row][128 f16] tiles, 256B rows, XOR-16B swizzle
//   byte(r, cb) = r*256 + (cb ^ ((r&7)<<4)) ):
//  B_hi 0 (32 KB)  (Bt[n][k] = fp16(W[k][n]), hi only)
//  A per group g (32 edges, hi 8KB + lo 8KB): 32768 + g*16384 (+8192 for lo)
//  bias 131072
#define SM_BHI 0
#define SM_A(g, part) (32768 + (g) * 16384 + (part) * 8192)
#define SM_BIAS 131072
#define SMEM_DYN (131072 + 512)

#define NGROUPS 6
#define TILE_E 32

__global__ void __launch_bounds__(384, 1) msg_kernel(
    const float* __restrict__ xs, const float* __restrict__ xd,
    const float* __restrict__ W, const float* __restrict__ bias,
    const int* __restrict__ src, const int* __restrict__ dst,
    int E, float* __restrict__ agg)
{
    extern __shared__ char smc[];

    const int tid  = threadIdx.x;
    const int wid  = tid >> 5;
    const int lane = tid & 31;
    const int g    = wid >> 1;          // warp-group 0..5 (2 warps each)
    const int wn   = wid & 1;           // N half: cols wn*64..wn*64+63
    const uint32_t sbase = smem_u32(smc);

    // ---- one-time W prep: Bt[n][k] = fp16(W[k][n]) ----
    for (int idx = tid; idx < 128 * 128; idx += 384) {
        int k = idx >> 7, n = idx & 127;
        __half hb = __float2half_rn(W[idx]);
        uint32_t off = (uint32_t)n * 256u + (((uint32_t)k * 2u) ^ (uint32_t)((n & 7) << 4));
        *(__half*)(smc + SM_BHI + off) = hb;
    }
    if (tid < 128) ((float*)(smc + SM_BIAS))[tid] = bias[tid];
    __syncthreads();
    const float* bias_sh = (const float*)(smc + SM_BIAS);

    // lane-fixed ldmatrix address components
    const uint32_t xr = (uint32_t)((lane & 7) << 4);
    const int rA_lo = ((lane >> 3) & 1) * 8 + (lane & 7);   // + ms*16
    const uint32_t kselA = (uint32_t)((lane >> 4) * 16);
    // B x4: m0/m1 = rows n0..n0+7 at k0/k8; m2/m3 = rows n0+8..n0+15 at k0/k8
    const int rB = ((lane >> 4) & 1) * 8 + (lane & 7);
    const uint32_t kselB = (uint32_t)(((lane >> 3) & 1) * 16);

    char* Ahc = smc + SM_A(g, 0);
    char* Alc = smc + SM_A(g, 1);
    const uint32_t AhU = sbase + SM_A(g, 0);
    const uint32_t AlU = sbase + SM_A(g, 1);

    const int numTiles = (E + TILE_E - 1) >> 5;
    const int stride = (int)gridDim.x * NGROUPS;
    for (int tile = blockIdx.x * NGROUPS + g; tile < numTiles; tile += stride) {
        const int ebase = tile * TILE_E;

        // ---- per-warp edge index fetch (no smem, no barrier):
        // lane<16: src of edge 2*lane+wn;  lane>=16: dst of edge 2*(lane-16)+wn
        int eg16 = ebase + 2 * (lane & 15) + wn;
        int idxv;
        if (eg16 < E) idxv = (lane < 16) ? src[eg16] : dst[eg16];
        else          idxv = (lane < 16) ? 0 : -1;

        GBAR(g);   // group's prior MMA done reading A

        // ---- fill A rows e = 2*it + wn (this warp's 16 rows), fp16 hi/lo ----
        #pragma unroll
        for (int ch = 0; ch < 2; ch++) {
            float4 av[8], cv[8];
            #pragma unroll
            for (int j = 0; j < 8; j++) {
                int it = ch * 8 + j;
                int sI = __shfl_sync(0xffffffffu, idxv, it);
                int dI = __shfl_sync(0xffffffffu, idxv, 16 + it);
                if (dI >= 0) {
                    av[j] = ((const float4*)(xs + (size_t)sI * 128))[lane];
                    cv[j] = ((const float4*)(xd + (size_t)dI * 128))[lane];
                } else {
                    av[j] = make_float4(0.f, 0.f, 0.f, 0.f);
                    cv[j] = av[j];
                }
            }
            #pragma unroll
            for (int j = 0; j < 8; j++) {
                int e = 2 * (ch * 8 + j) + wn;   // edge row 0..31
                float4 p;
                p.x = av[j].x * cv[j].x; p.y = av[j].y * cv[j].y;
                p.z = av[j].z * cv[j].z; p.w = av[j].w * cv[j].w;
                __half2 h01 = __float22half2_rn(make_float2(p.x, p.y));
                __half2 h23 = __float22half2_rn(make_float2(p.z, p.w));
                float2 f01 = __half22float2(h01);
                float2 f23 = __half22float2(h23);
                __half2 l01 = __float22half2_rn(make_float2(p.x - f01.x, p.y - f01.y));
                __half2 l23 = __float22half2_rn(make_float2(p.z - f23.x, p.w - f23.y));
                uint32_t off = (uint32_t)e * 256u + (((uint32_t)lane * 8u) ^ (uint32_t)((e & 7) << 4));
                *(uint2*)(Ahc + off) = make_uint2(*(uint32_t*)&h01, *(uint32_t*)&h23);
                *(uint2*)(Alc + off) = make_uint2(*(uint32_t*)&l01, *(uint32_t*)&l23);
            }
        }
        GBAR(g);   // A tile complete (both warps)

        // ---- warp tile M32 x N64: acc[ms 2][nb 8][4], 2-pass fp16 split ----
        {
            float acc[2][8][4];
            #pragma unroll
            for (int ms = 0; ms < 2; ms++)
                #pragma unroll
                for (int nb = 0; nb < 8; nb++)
                    #pragma unroll
                    for (int q = 0; q < 4; q++) acc[ms][nb][q] = 0.f;

            #pragma unroll
            for (int ks = 0; ks < 8; ks++) {
                uint32_t Ah[2][4], Al[2][4];
                #pragma unroll
                for (int ms = 0; ms < 2; ms++) {
                    uint32_t r = (uint32_t)(rA_lo + ms * 16);
                    uint32_t off = r * 256u + (((uint32_t)(ks * 32) + kselA) ^ xr);
                    ldm_x4(Ah[ms], AhU + off);
                    ldm_x4(Al[ms], AlU + off);
                }
                #pragma unroll
                for (int nbp = 0; nbp < 4; nbp++) {   // pair of n8 blocks
                    uint32_t n0 = (uint32_t)(wn * 64 + nbp * 16 + rB);
                    uint32_t off = n0 * 256u + (((uint32_t)(ks * 32) + kselB) ^ xr);
                    uint32_t Bh4[4];
                    ldm_x4(Bh4, sbase + SM_BHI + off);
                    #pragma unroll
                    for (int half = 0; half < 2; half++) {
                        int nb = nbp * 2 + half;
                        #pragma unroll
                        for (int ms = 0; ms < 2; ms++) {
                            mma_f16(acc[ms][nb], Ah[ms], Bh4 + half * 2);
                            mma_f16(acc[ms][nb], Al[ms], Bh4 + half * 2);
                        }
                    }
                }
            }

            // ---- epilogue: bias + LeakyReLU + shfl-pair into red.v4 ----
            #pragma unroll
            for (int ms = 0; ms < 2; ms++) {
                int e_lo = ms * 16 + (lane >> 2);
                int eg0 = ebase + e_lo;
                int eg1 = ebase + e_lo + 8;
                int dn0 = (eg0 < E) ? dst[eg0] : -1;
                int dn1 = (eg1 < E) ? dst[eg1] : -1;
                #pragma unroll
                for (int nb = 0; nb < 8; nb++) {
                    int cb = wn * 64 + nb * 8 + 2 * (lane & 3);
                    float b0 = bias_sh[cb], b1 = bias_sh[cb + 1];
                    float m0 = lrelu(acc[ms][nb][0] + b0);
                    float m1 = lrelu(acc[ms][nb][1] + b1);
                    float m2 = lrelu(acc[ms][nb][2] + b0);
                    float m3 = lrelu(acc[ms][nb][3] + b1);
                    float s0 = __shfl_xor_sync(0xffffffffu, m0, 1);
                    float s1 = __shfl_xor_sync(0xffffffffu, m1, 1);
                    float s2 = __shfl_xor_sync(0xffffffffu, m2, 1);
                    float s3 = __shfl_xor_sync(0xffffffffu, m3, 1);
                    if ((lane & 1) == 0) {
                        if (dn0 >= 0) {
                            float* ptr = agg + (size_t)dn0 * 128 + cb;
                            asm volatile("red.global.add.v4.f32 [%0], {%1, %2, %3, %4};"
                                         :: "l"(ptr), "f"(m0), "f"(m1), "f"(s0), "f"(s1)
                                         : "memory");
                        }
                        if (dn1 >= 0) {
                            float* ptr = agg + (size_t)dn1 * 128 + cb;
                            asm volatile("red.global.add.v4.f32 [%0], {%1, %2, %3, %4};"
                                         :: "l"(ptr), "f"(m2), "f"(m3), "f"(s2), "f"(s3)
                                         : "memory");
                        }
                    }
                }
            }
        }
    }
}

// ---------------------------------------------------------------------------
// In-place LayerNorm + ReLU. One warp per node.
// ---------------------------------------------------------------------------
__global__ void ln_relu_kernel(float* __restrict__ x,
                               const float* __restrict__ w,
                               const float* __restrict__ b, int N)
{
    int gw = (int)((blockIdx.x * blockDim.x + threadIdx.x) >> 5);
    int lane = threadIdx.x & 31;
    if (gw >= N) return;

    float4 v = ((const float4*)(x + (size_t)gw * 128))[lane];
    float s = v.x + v.y + v.z + v.w;
    #pragma unroll
    for (int o = 16; o; o >>= 1) s += __shfl_xor_sync(0xffffffffu, s, o);
    float mu = s * (1.f / 128.f);

    float dx = v.x - mu, dy = v.y - mu, dz = v.z - mu, dw = v.w - mu;
    float q = dx * dx + dy * dy + dz * dz + dw * dw;
    #pragma unroll
    for (int o = 16; o; o >>= 1) q += __shfl_xor_sync(0xffffffffu, q, o);
    float rs = rsqrtf(q * (1.f / 128.f) + LN_EPS);

    float4 wv = ((const float4*)w)[lane];
    float4 bv = ((const float4*)b)[lane];
    float4 r;
    r.x = fmaxf(dx * rs * wv.x + bv.x, 0.f);
    r.y = fmaxf(dy * rs * wv.y + bv.y, 0.f);
    r.z = fmaxf(dz * rs * wv.z + bv.z, 0.f);
    r.w = fmaxf(dw * rs * wv.w + bv.w, 0.f);
    ((float4*)(x + (size_t)gw * 128))[lane] = r;
}

// ---------------------------------------------------------------------------
extern "C" void kernel_launch(void* const* d_in, const int* in_sizes, int n_in,
                              void* d_out, int out_size)
{
    const float* x_user = (const float*)d_in[0];
    const float* x_item = (const float*)d_in[1];
    const float* W_ui   = (const float*)d_in[2];
    const float* b_ui   = (const float*)d_in[3];
    const float* W_iu   = (const float*)d_in[4];
    const float* b_iu   = (const float*)d_in[5];
    const float* lnw_u  = (const float*)d_in[6];
    const float* lnb_u  = (const float*)d_in[7];
    const float* lnw_i  = (const float*)d_in[8];
    const float* lnb_i  = (const float*)d_in[9];
    const int* es_ui = (const int*)d_in[10];
    const int* ed_ui = (const int*)d_in[11];
    const int* es_iu = (const int*)d_in[12];
    const int* ed_iu = (const int*)d_in[13];

    const int n_user = in_sizes[0] / 128;
    const int n_item = in_sizes[1] / 128;
    const int E_ui = in_sizes[10];
    const int E_iu = in_sizes[12];

    float* out = (float*)d_out;
    float* agg_user = out;
    float* agg_item = out + (size_t)n_user * 128;

    // slot shifter so ncu's skip-count lands on msg_kernel
    dummy_kernel<<<1, 32>>>((int*)0);

    long n4 = ((long)n_user + n_item) * 128 / 4;
    zero_kernel<<<4096, 256>>>((float4*)out, n4);

    cudaFuncSetAttribute(msg_kernel,
                         cudaFuncAttributeMaxDynamicSharedMemorySize, SMEM_DYN);
    msg_kernel<<<148, 384, SMEM_DYN>>>(x_user, x_item, W_ui, b_ui,
                                       es_ui, ed_ui, E_ui, agg_item);
    msg_kernel<<<148, 384, SMEM_DYN>>>(x_item, x_user, W_iu, b_iu,
                                       es_iu, ed_iu, E_iu, agg_user);

    ln_relu_kernel<<<(n_user + 7) / 8, 256>>>(agg_user, lnw_u, lnb_u, n_user);
    ln_relu_kernel<<<(n_item + 7) / 8, 256>>>(agg_item, lnw_i, lnb_i, n_item);

    (void)n_in; (void)out_size;
}

// round 11
// speedup vs baseline: 3.0846x; 1.0887x over previous
#include <cuda_runtime.h>
#include <cuda_fp16.h>
#include <cstdint>

#define NEG_SLOPE 0.01f
#define LN_EPS 1e-5f

__device__ __forceinline__ float lrelu(float x) { return fmaxf(x, NEG_SLOPE * x); }

__device__ __forceinline__ uint32_t smem_u32(const void* p) {
    uint32_t a;
    asm("{ .reg .u64 t; cvta.to.shared.u64 t, %1; cvt.u32.u64 %0, t; }" : "=r"(a) : "l"(p));
    return a;
}
__device__ __forceinline__ void ldm_x4(uint32_t r[4], uint32_t a) {
    asm volatile("ldmatrix.sync.aligned.m8n8.x4.shared.b16 {%0,%1,%2,%3}, [%4];"
                 : "=r"(r[0]), "=r"(r[1]), "=r"(r[2]), "=r"(r[3]) : "r"(a) : "memory");
}
__device__ __forceinline__ void mma_f16(float* d, const uint32_t* a, const uint32_t* b) {
    asm volatile("mma.sync.aligned.m16n8k16.row.col.f32.f16.f16.f32 "
                 "{%0,%1,%2,%3}, {%4,%5,%6,%7}, {%8,%9}, {%0,%1,%2,%3};"
                 : "+f"(d[0]), "+f"(d[1]), "+f"(d[2]), "+f"(d[3])
                 : "r"(a[0]), "r"(a[1]), "r"(a[2]), "r"(a[3]), "r"(b[0]), "r"(b[1]));
}
// 64-thread group barrier, ids 1..8
#define GBAR(g) asm volatile("bar.sync %0, %1;" :: "r"((g) + 1), "r"(64) : "memory")

// ============================ kernels ============================
__global__ void dummy_kernel(int* p) { if (p) *p = 0; }   // ncu slot shifter (p==NULL)

__global__ void zero_kernel(float4* __restrict__ p, long n4) {
    long i = (long)blockIdx.x * blockDim.x + threadIdx.x;
    long stride = (long)gridDim.x * blockDim.x;
    float4 z = make_float4(0.f, 0.f, 0.f, 0.f);
    for (; i < n4; i += stride) p[i] = z;
}

// Shared layout (row-major [row][128 f16] tiles, 256B rows, XOR-16B swizzle
//   byte(r, cb) = r*256 + (cb ^ ((r&7)<<4)) ):
//  B_hi 0 (32 KB)  (Bt[n][k] = fp16(W[k][n]))
//  A per group g (32 edges, hi 8KB + lo 8KB): 32768 + g*16384 (+8192 for lo)
//  bias 163840
#define SM_BHI 0
#define SM_A(g, part) (32768 + (g) * 16384 + (part) * 8192)
#define SM_BIAS 163840
#define SMEM_DYN (163840 + 512)

#define NGROUPS 8
#define NTHREADS 512
#define TILE_E 32

__global__ void __launch_bounds__(NTHREADS, 1) msg_kernel(
    const float* __restrict__ xs, const float* __restrict__ xd,
    const float* __restrict__ W, const float* __restrict__ bias,
    const int* __restrict__ src, const int* __restrict__ dst,
    int E, float* __restrict__ agg)
{
    extern __shared__ char smc[];

    const int tid  = threadIdx.x;
    const int wid  = tid >> 5;
    const int lane = tid & 31;
    const int g    = wid >> 1;          // warp-group 0..7 (2 warps each)
    const int wn   = wid & 1;           // N half: cols wn*64..wn*64+63
    const uint32_t sbase = smem_u32(smc);

    // ---- one-time W prep: Bt[n][k] = fp16(W[k][n]) ----
    for (int idx = tid; idx < 128 * 128; idx += NTHREADS) {
        int k = idx >> 7, n = idx & 127;
        __half hb = __float2half_rn(W[idx]);
        uint32_t off = (uint32_t)n * 256u + (((uint32_t)k * 2u) ^ (uint32_t)((n & 7) << 4));
        *(__half*)(smc + SM_BHI + off) = hb;
    }
    if (tid < 128) ((float*)(smc + SM_BIAS))[tid] = bias[tid];
    __syncthreads();
    const float* bias_sh = (const float*)(smc + SM_BIAS);

    // lane-fixed ldmatrix address components
    const uint32_t xr = (uint32_t)((lane & 7) << 4);
    const int rA_lo = ((lane >> 3) & 1) * 8 + (lane & 7);   // + ms*16
    const uint32_t kselA = (uint32_t)((lane >> 4) * 16);
    // B x4: m0/m1 = rows n0..n0+7 at k0/k8; m2/m3 = rows n0+8..n0+15 at k0/k8
    const int rB = ((lane >> 4) & 1) * 8 + (lane & 7);
    const uint32_t kselB = (uint32_t)(((lane >> 3) & 1) * 16);

    char* Ahc = smc + SM_A(g, 0);
    char* Alc = smc + SM_A(g, 1);
    const uint32_t AhU = sbase + SM_A(g, 0);
    const uint32_t AlU = sbase + SM_A(g, 1);

    const int numTiles = (E + TILE_E - 1) >> 5;
    const int stride = (int)gridDim.x * NGROUPS;
    for (int tile = blockIdx.x * NGROUPS + g; tile < numTiles; tile += stride) {
        const int ebase = tile * TILE_E;

        // ---- per-warp edge index fetch (no smem, no barrier):
        // lane<16: src of edge 2*lane+wn;  lane>=16: dst of edge 2*(lane-16)+wn
        int eg16 = ebase + 2 * (lane & 15) + wn;
        int idxv;
        if (eg16 < E) idxv = (lane < 16) ? src[eg16] : dst[eg16];
        else          idxv = (lane < 16) ? 0 : -1;

        GBAR(g);   // group's prior MMA done reading A

        // ---- fill A rows e = 2*it + wn (this warp's 16 rows), fp16 hi/lo ----
        #pragma unroll
        for (int ch = 0; ch < 4; ch++) {
            float4 av[4], cv[4];
            #pragma unroll
            for (int j = 0; j < 4; j++) {
                int it = ch * 4 + j;
                int sI = __shfl_sync(0xffffffffu, idxv, it);
                int dI = __shfl_sync(0xffffffffu, idxv, 16 + it);
                if (dI >= 0) {
                    av[j] = ((const float4*)(xs + (size_t)sI * 128))[lane];
                    cv[j] = ((const float4*)(xd + (size_t)dI * 128))[lane];
                } else {
                    av[j] = make_float4(0.f, 0.f, 0.f, 0.f);
                    cv[j] = av[j];
                }
            }
            #pragma unroll
            for (int j = 0; j < 4; j++) {
                int e = 2 * (ch * 4 + j) + wn;   // edge row 0..31
                float4 p;
                p.x = av[j].x * cv[j].x; p.y = av[j].y * cv[j].y;
                p.z = av[j].z * cv[j].z; p.w = av[j].w * cv[j].w;
                __half2 h01 = __float22half2_rn(make_float2(p.x, p.y));
                __half2 h23 = __float22half2_rn(make_float2(p.z, p.w));
                float2 f01 = __half22float2(h01);
                float2 f23 = __half22float2(h23);
                __half2 l01 = __float22half2_rn(make_float2(p.x - f01.x, p.y - f01.y));
                __half2 l23 = __float22half2_rn(make_float2(p.z - f23.x, p.w - f23.y));
                uint32_t off = (uint32_t)e * 256u + (((uint32_t)lane * 8u) ^ (uint32_t)((e & 7) << 4));
                *(uint2*)(Ahc + off) = make_uint2(*(uint32_t*)&h01, *(uint32_t*)&h23);
                *(uint2*)(Alc + off) = make_uint2(*(uint32_t*)&l01, *(uint32_t*)&l23);
            }
        }
        GBAR(g);   // A tile complete (both warps)

        // ---- warp tile M32 x N64: acc[ms 2][nb 8][4], 2-pass fp16 split ----
        {
            float acc[2][8][4];
            #pragma unroll
            for (int ms = 0; ms < 2; ms++)
                #pragma unroll
                for (int nb = 0; nb < 8; nb++)
                    #pragma unroll
                    for (int q = 0; q < 4; q++) acc[ms][nb][q] = 0.f;

            #pragma unroll
            for (int ks = 0; ks < 8; ks++) {
                uint32_t Ah[2][4], Al[2][4];
                #pragma unroll
                for (int ms = 0; ms < 2; ms++) {
                    uint32_t r = (uint32_t)(rA_lo + ms * 16);
                    uint32_t off = r * 256u + (((uint32_t)(ks * 32) + kselA) ^ xr);
                    ldm_x4(Ah[ms], AhU + off);
                    ldm_x4(Al[ms], AlU + off);
                }
                #pragma unroll
                for (int nbp = 0; nbp < 4; nbp++) {   // pair of n8 blocks
                    uint32_t n0 = (uint32_t)(wn * 64 + nbp * 16 + rB);
                    uint32_t off = n0 * 256u + (((uint32_t)(ks * 32) + kselB) ^ xr);
                    uint32_t Bh4[4];
                    ldm_x4(Bh4, sbase + SM_BHI + off);
                    #pragma unroll
                    for (int half = 0; half < 2; half++) {
                        int nb = nbp * 2 + half;
                        #pragma unroll
                        for (int ms = 0; ms < 2; ms++) {
                            mma_f16(acc[ms][nb], Ah[ms], Bh4 + half * 2);
                            mma_f16(acc[ms][nb], Al[ms], Bh4 + half * 2);
                        }
                    }
                }
            }

            // ---- epilogue: bias + LeakyReLU + shfl-pair into red.v4 ----
            #pragma unroll
            for (int ms = 0; ms < 2; ms++) {
                int e_lo = ms * 16 + (lane >> 2);
                int eg0 = ebase + e_lo;
                int eg1 = ebase + e_lo + 8;
                int dn0 = (eg0 < E) ? dst[eg0] : -1;
                int dn1 = (eg1 < E) ? dst[eg1] : -1;
                #pragma unroll
                for (int nb = 0; nb < 8; nb++) {
                    int cb = wn * 64 + nb * 8 + 2 * (lane & 3);
                    float b0 = bias_sh[cb], b1 = bias_sh[cb + 1];
                    float m0 = lrelu(acc[ms][nb][0] + b0);
                    float m1 = lrelu(acc[ms][nb][1] + b1);
                    float m2 = lrelu(acc[ms][nb][2] + b0);
                    float m3 = lrelu(acc[ms][nb][3] + b1);
                    float s0 = __shfl_xor_sync(0xffffffffu, m0, 1);
                    float s1 = __shfl_xor_sync(0xffffffffu, m1, 1);
                    float s2 = __shfl_xor_sync(0xffffffffu, m2, 1);
                    float s3 = __shfl_xor_sync(0xffffffffu, m3, 1);
                    if ((lane & 1) == 0) {
                        if (dn0 >= 0) {
                            float* ptr = agg + (size_t)dn0 * 128 + cb;
                            asm volatile("red.global.add.v4.f32 [%0], {%1, %2, %3, %4};"
                                         :: "l"(ptr), "f"(m0), "f"(m1), "f"(s0), "f"(s1)
                                         : "memory");
                        }
                        if (dn1 >= 0) {
                            float* ptr = agg + (size_t)dn1 * 128 + cb;
                            asm volatile("red.global.add.v4.f32 [%0], {%1, %2, %3, %4};"
                                         :: "l"(ptr), "f"(m2), "f"(m3), "f"(s2), "f"(s3)
                                         : "memory");
                        }
                    }
                }
            }
        }
    }
}

// ---------------------------------------------------------------------------
// In-place LayerNorm + ReLU. One warp per node.
// ---------------------------------------------------------------------------
__global__ void ln_relu_kernel(float* __restrict__ x,
                               const float* __restrict__ w,
                               const float* __restrict__ b, int N)
{
    int gw = (int)((blockIdx.x * blockDim.x + threadIdx.x) >> 5);
    int lane = threadIdx.x & 31;
    if (gw >= N) return;

    float4 v = ((const float4*)(x + (size_t)gw * 128))[lane];
    float s = v.x + v.y + v.z + v.w;
    #pragma unroll
    for (int o = 16; o; o >>= 1) s += __shfl_xor_sync(0xffffffffu, s, o);
    float mu = s * (1.f / 128.f);

    float dx = v.x - mu, dy = v.y - mu, dz = v.z - mu, dw = v.w - mu;
    float q = dx * dx + dy * dy + dz * dz + dw * dw;
    #pragma unroll
    for (int o = 16; o; o >>= 1) q += __shfl_xor_sync(0xffffffffu, q, o);
    float rs = rsqrtf(q * (1.f / 128.f) + LN_EPS);

    float4 wv = ((const float4*)w)[lane];
    float4 bv = ((const float4*)b)[lane];
    float4 r;
    r.x = fmaxf(dx * rs * wv.x + bv.x, 0.f);
    r.y = fmaxf(dy * rs * wv.y + bv.y, 0.f);
    r.z = fmaxf(dz * rs * wv.z + bv.z, 0.f);
    r.w = fmaxf(dw * rs * wv.w + bv.w, 0.f);
    ((float4*)(x + (size_t)gw * 128))[lane] = r;
}

// ---------------------------------------------------------------------------
extern "C" void kernel_launch(void* const* d_in, const int* in_sizes, int n_in,
                              void* d_out, int out_size)
{
    const float* x_user = (const float*)d_in[0];
    const float* x_item = (const float*)d_in[1];
    const float* W_ui   = (const float*)d_in[2];
    const float* b_ui   = (const float*)d_in[3];
    const float* W_iu   = (const float*)d_in[4];
    const float* b_iu   = (const float*)d_in[5];
    const float* lnw_u  = (const float*)d_in[6];
    const float* lnb_u  = (const float*)d_in[7];
    const float* lnw_i  = (const float*)d_in[8];
    const float* lnb_i  = (const float*)d_in[9];
    const int* es_ui = (const int*)d_in[10];
    const int* ed_ui = (const int*)d_in[11];
    const int* es_iu = (const int*)d_in[12];
    const int* ed_iu = (const int*)d_in[13];

    const int n_user = in_sizes[0] / 128;
    const int n_item = in_sizes[1] / 128;
    const int E_ui = in_sizes[10];
    const int E_iu = in_sizes[12];

    float* out = (float*)d_out;
    float* agg_user = out;
    float* agg_item = out + (size_t)n_user * 128;

    // slot shifter so ncu's skip-count lands on msg_kernel
    dummy_kernel<<<1, 32>>>((int*)0);

    long n4 = ((long)n_user + n_item) * 128 / 4;
    zero_kernel<<<4096, 256>>>((float4*)out, n4);

    cudaFuncSetAttribute(msg_kernel,
                         cudaFuncAttributeMaxDynamicSharedMemorySize, SMEM_DYN);
    msg_kernel<<<148, NTHREADS, SMEM_DYN>>>(x_user, x_item, W_ui, b_ui,
                                            es_ui, ed_ui, E_ui, agg_item);
    msg_kernel<<<148, NTHREADS, SMEM_DYN>>>(x_item, x_user, W_iu, b_iu,
                                            es_iu, ed_iu, E_iu, agg_user);

    ln_relu_kernel<<<(n_user + 7) / 8, 256>>>(agg_user, lnw_u, lnb_u, n_user);
    ln_relu_kernel<<<(n_item + 7) / 8, 256>>>(agg_item, lnw_i, lnb_i, n_item);

    (void)n_in; (void)out_size;
}

// round 12
// speedup vs baseline: 3.4377x; 1.1145x over previous
#include <cuda_runtime.h>
#include <cuda_fp16.h>
#include <cstdint>

#define NEG_SLOPE 0.01f
#define LN_EPS 1e-5f

__device__ __forceinline__ float lrelu(float x) { return fmaxf(x, NEG_SLOPE * x); }

__device__ __forceinline__ uint32_t smem_u32(const void* p) {
    uint32_t a;
    asm("{ .reg .u64 t; cvta.to.shared.u64 t, %1; cvt.u32.u64 %0, t; }" : "=r"(a) : "l"(p));
    return a;
}
__device__ __forceinline__ void ldm_x4(uint32_t r[4], uint32_t a) {
    asm volatile("ldmatrix.sync.aligned.m8n8.x4.shared.b16 {%0,%1,%2,%3}, [%4];"
                 : "=r"(r[0]), "=r"(r[1]), "=r"(r[2]), "=r"(r[3]) : "r"(a) : "memory");
}
__device__ __forceinline__ void mma_f16(float* d, const uint32_t* a, const uint32_t* b) {
    asm volatile("mma.sync.aligned.m16n8k16.row.col.f32.f16.f16.f32 "
                 "{%0,%1,%2,%3}, {%4,%5,%6,%7}, {%8,%9}, {%0,%1,%2,%3};"
                 : "+f"(d[0]), "+f"(d[1]), "+f"(d[2]), "+f"(d[3])
                 : "r"(a[0]), "r"(a[1]), "r"(a[2]), "r"(a[3]), "r"(b[0]), "r"(b[1]));
}
// 64-thread group barrier, ids 1..10
#define GBAR(g) asm volatile("bar.sync %0, %1;" :: "r"((g) + 1), "r"(64) : "memory")

// ============================ kernels ============================
__global__ void dummy_kernel(int* p) { if (p) *p = 0; }   // ncu slot shifter (p==NULL)

__global__ void zero_kernel(float4* __restrict__ p, long n4) {
    long i = (long)blockIdx.x * blockDim.x + threadIdx.x;
    long stride = (long)gridDim.x * blockDim.x;
    float4 z = make_float4(0.f, 0.f, 0.f, 0.f);
    for (; i < n4; i += stride) p[i] = z;
}

// Shared layout (row-major [row][128 f16] tiles, 256B rows, XOR-16B swizzle
//   byte(r, cb) = r*256 + (cb ^ ((r&7)<<4)) ):
//  B_hi 0 (32 KB)  (Bt[n][k] = fp16(W[k][n]))
//  A per group g (32 edges, fp16): 32768 + g*8192
//  bias 114688
#define SM_BHI 0
#define SM_A(g) (32768 + (g) * 8192)
#define SM_BIAS 114688
#define SMEM_DYN (114688 + 512)

#define NGROUPS 10
#define NTHREADS 640
#define TILE_E 32

__global__ void __launch_bounds__(NTHREADS, 1) msg_kernel(
    const float* __restrict__ xs, const float* __restrict__ xd,
    const float* __restrict__ W, const float* __restrict__ bias,
    const int* __restrict__ src, const int* __restrict__ dst,
    int E, float* __restrict__ agg)
{
    extern __shared__ char smc[];

    const int tid  = threadIdx.x;
    const int wid  = tid >> 5;
    const int lane = tid & 31;
    const int g    = wid >> 1;          // warp-group 0..9 (2 warps each)
    const int wn   = wid & 1;           // N half: cols wn*64..wn*64+63
    const uint32_t sbase = smem_u32(smc);

    // ---- one-time W prep: Bt[n][k] = fp16(W[k][n]) ----
    for (int idx = tid; idx < 128 * 128; idx += NTHREADS) {
        int k = idx >> 7, n = idx & 127;
        __half hb = __float2half_rn(W[idx]);
        uint32_t off = (uint32_t)n * 256u + (((uint32_t)k * 2u) ^ (uint32_t)((n & 7) << 4));
        *(__half*)(smc + SM_BHI + off) = hb;
    }
    if (tid < 128) ((float*)(smc + SM_BIAS))[tid] = bias[tid];
    __syncthreads();
    const float* bias_sh = (const float*)(smc + SM_BIAS);

    // lane-fixed ldmatrix address components
    const uint32_t xr = (uint32_t)((lane & 7) << 4);
    const int rA_lo = ((lane >> 3) & 1) * 8 + (lane & 7);   // + ms*16
    const uint32_t kselA = (uint32_t)((lane >> 4) * 16);
    // B x4: m0/m1 = rows n0..n0+7 at k0/k8; m2/m3 = rows n0+8..n0+15 at k0/k8
    const int rB = ((lane >> 4) & 1) * 8 + (lane & 7);
    const uint32_t kselB = (uint32_t)(((lane >> 3) & 1) * 16);

    char* Ahc = smc + SM_A(g);
    const uint32_t AhU = sbase + SM_A(g);

    const int numTiles = (E + TILE_E - 1) >> 5;
    const int stride = (int)gridDim.x * NGROUPS;
    for (int tile = blockIdx.x * NGROUPS + g; tile < numTiles; tile += stride) {
        const int ebase = tile * TILE_E;

        // ---- per-warp edge index fetch (no smem, no barrier):
        // lane<16: src of edge 2*lane+wn;  lane>=16: dst of edge 2*(lane-16)+wn
        int eg16 = ebase + 2 * (lane & 15) + wn;
        int idxv;
        if (eg16 < E) idxv = (lane < 16) ? src[eg16] : dst[eg16];
        else          idxv = (lane < 16) ? 0 : -1;

        GBAR(g);   // group's prior MMA done reading A

        // ---- fill A rows e = 2*it + wn (this warp's 16 rows), fp16 ----
        #pragma unroll
        for (int ch = 0; ch < 4; ch++) {
            float4 av[4], cv[4];
            #pragma unroll
            for (int j = 0; j < 4; j++) {
                int it = ch * 4 + j;
                int sI = __shfl_sync(0xffffffffu, idxv, it);
                int dI = __shfl_sync(0xffffffffu, idxv, 16 + it);
                if (dI >= 0) {
                    av[j] = ((const float4*)(xs + (size_t)sI * 128))[lane];
                    cv[j] = ((const float4*)(xd + (size_t)dI * 128))[lane];
                } else {
                    av[j] = make_float4(0.f, 0.f, 0.f, 0.f);
                    cv[j] = av[j];
                }
            }
            #pragma unroll
            for (int j = 0; j < 4; j++) {
                int e = 2 * (ch * 4 + j) + wn;   // edge row 0..31
                float4 p;
                p.x = av[j].x * cv[j].x; p.y = av[j].y * cv[j].y;
                p.z = av[j].z * cv[j].z; p.w = av[j].w * cv[j].w;
                __half2 h01 = __float22half2_rn(make_float2(p.x, p.y));
                __half2 h23 = __float22half2_rn(make_float2(p.z, p.w));
                uint32_t off = (uint32_t)e * 256u + (((uint32_t)lane * 8u) ^ (uint32_t)((e & 7) << 4));
                *(uint2*)(Ahc + off) = make_uint2(*(uint32_t*)&h01, *(uint32_t*)&h23);
            }
        }
        GBAR(g);   // A tile complete (both warps)

        // ---- warp tile M32 x N64: acc[ms 2][nb 8][4], single-pass fp16 ----
        {
            float acc[2][8][4];
            #pragma unroll
            for (int ms = 0; ms < 2; ms++)
                #pragma unroll
                for (int nb = 0; nb < 8; nb++)
                    #pragma unroll
                    for (int q = 0; q < 4; q++) acc[ms][nb][q] = 0.f;

            #pragma unroll
            for (int ks = 0; ks < 8; ks++) {
                uint32_t Ah[2][4];
                #pragma unroll
                for (int ms = 0; ms < 2; ms++) {
                    uint32_t r = (uint32_t)(rA_lo + ms * 16);
                    uint32_t off = r * 256u + (((uint32_t)(ks * 32) + kselA) ^ xr);
                    ldm_x4(Ah[ms], AhU + off);
                }
                #pragma unroll
                for (int nbp = 0; nbp < 4; nbp++) {   // pair of n8 blocks
                    uint32_t n0 = (uint32_t)(wn * 64 + nbp * 16 + rB);
                    uint32_t off = n0 * 256u + (((uint32_t)(ks * 32) + kselB) ^ xr);
                    uint32_t Bh4[4];
                    ldm_x4(Bh4, sbase + SM_BHI + off);
                    #pragma unroll
                    for (int half = 0; half < 2; half++) {
                        int nb = nbp * 2 + half;
                        #pragma unroll
                        for (int ms = 0; ms < 2; ms++)
                            mma_f16(acc[ms][nb], Ah[ms], Bh4 + half * 2);
                    }
                }
            }

            // ---- epilogue: bias + LeakyReLU + shfl-pair into red.v4 ----
            #pragma unroll
            for (int ms = 0; ms < 2; ms++) {
                int e_lo = ms * 16 + (lane >> 2);
                int eg0 = ebase + e_lo;
                int eg1 = ebase + e_lo + 8;
                int dn0 = (eg0 < E) ? dst[eg0] : -1;
                int dn1 = (eg1 < E) ? dst[eg1] : -1;
                #pragma unroll
                for (int nb = 0; nb < 8; nb++) {
                    int cb = wn * 64 + nb * 8 + 2 * (lane & 3);
                    float b0 = bias_sh[cb], b1 = bias_sh[cb + 1];
                    float m0 = lrelu(acc[ms][nb][0] + b0);
                    float m1 = lrelu(acc[ms][nb][1] + b1);
                    float m2 = lrelu(acc[ms][nb][2] + b0);
                    float m3 = lrelu(acc[ms][nb][3] + b1);
                    float s0 = __shfl_xor_sync(0xffffffffu, m0, 1);
                    float s1 = __shfl_xor_sync(0xffffffffu, m1, 1);
                    float s2 = __shfl_xor_sync(0xffffffffu, m2, 1);
                    float s3 = __shfl_xor_sync(0xffffffffu, m3, 1);
                    if ((lane & 1) == 0) {
                        if (dn0 >= 0) {
                            float* ptr = agg + (size_t)dn0 * 128 + cb;
                            asm volatile("red.global.add.v4.f32 [%0], {%1, %2, %3, %4};"
                                         :: "l"(ptr), "f"(m0), "f"(m1), "f"(s0), "f"(s1)
                                         : "memory");
                        }
                        if (dn1 >= 0) {
                            float* ptr = agg + (size_t)dn1 * 128 + cb;
                            asm volatile("red.global.add.v4.f32 [%0], {%1, %2, %3, %4};"
                                         :: "l"(ptr), "f"(m2), "f"(m3), "f"(s2), "f"(s3)
                                         : "memory");
                        }
                    }
                }
            }
        }
    }
}

// ---------------------------------------------------------------------------
// In-place LayerNorm + ReLU. One warp per node.
// ---------------------------------------------------------------------------
__global__ void ln_relu_kernel(float* __restrict__ x,
                               const float* __restrict__ w,
                               const float* __restrict__ b, int N)
{
    int gw = (int)((blockIdx.x * blockDim.x + threadIdx.x) >> 5);
    int lane = threadIdx.x & 31;
    if (gw >= N) return;

    float4 v = ((const float4*)(x + (size_t)gw * 128))[lane];
    float s = v.x + v.y + v.z + v.w;
    #pragma unroll
    for (int o = 16; o; o >>= 1) s += __shfl_xor_sync(0xffffffffu, s, o);
    float mu = s * (1.f / 128.f);

    float dx = v.x - mu, dy = v.y - mu, dz = v.z - mu, dw = v.w - mu;
    float q = dx * dx + dy * dy + dz * dz + dw * dw;
    #pragma unroll
    for (int o = 16; o; o >>= 1) q += __shfl_xor_sync(0xffffffffu, q, o);
    float rs = rsqrtf(q * (1.f / 128.f) + LN_EPS);

    float4 wv = ((const float4*)w)[lane];
    float4 bv = ((const float4*)b)[lane];
    float4 r;
    r.x = fmaxf(dx * rs * wv.x + bv.x, 0.f);
    r.y = fmaxf(dy * rs * wv.y + bv.y, 0.f);
    r.z = fmaxf(dz * rs * wv.z + bv.z, 0.f);
    r.w = fmaxf(dw * rs * wv.w + bv.w, 0.f);
    ((float4*)(x + (size_t)gw * 128))[lane] = r;
}

// ---------------------------------------------------------------------------
extern "C" void kernel_launch(void* const* d_in, const int* in_sizes, int n_in,
                              void* d_out, int out_size)
{
    const float* x_user = (const float*)d_in[0];
    const float* x_item = (const float*)d_in[1];
    const float* W_ui   = (const float*)d_in[2];
    const float* b_ui   = (const float*)d_in[3];
    const float* W_iu   = (const float*)d_in[4];
    const float* b_iu   = (const float*)d_in[5];
    const float* lnw_u  = (const float*)d_in[6];
    const float* lnb_u  = (const float*)d_in[7];
    const float* lnw_i  = (const float*)d_in[8];
    const float* lnb_i  = (const float*)d_in[9];
    const int* es_ui = (const int*)d_in[10];
    const int* ed_ui = (const int*)d_in[11];
    const int* es_iu = (const int*)d_in[12];
    const int* ed_iu = (const int*)d_in[13];

    const int n_user = in_sizes[0] / 128;
    const int n_item = in_sizes[1] / 128;
    const int E_ui = in_sizes[10];
    const int E_iu = in_sizes[12];

    float* out = (float*)d_out;
    float* agg_user = out;
    float* agg_item = out + (size_t)n_user * 128;

    // slot shifter so ncu's skip-count lands on msg_kernel
    dummy_kernel<<<1, 32>>>((int*)0);

    long n4 = ((long)n_user + n_item) * 128 / 4;
    zero_kernel<<<4096, 256>>>((float4*)out, n4);

    cudaFuncSetAttribute(msg_kernel,
                         cudaFuncAttributeMaxDynamicSharedMemorySize, SMEM_DYN);
    msg_kernel<<<148, NTHREADS, SMEM_DYN>>>(x_user, x_item, W_ui, b_ui,
                                            es_ui, ed_ui, E_ui, agg_item);
    msg_kernel<<<148, NTHREADS, SMEM_DYN>>>(x_item, x_user, W_iu, b_iu,
                                            es_iu, ed_iu, E_iu, agg_user);

    ln_relu_kernel<<<(n_user + 7) / 8, 256>>>(agg_user, lnw_u, lnb_u, n_user);
    ln_relu_kernel<<<(n_item + 7) / 8, 256>>>(agg_item, lnw_i, lnb_i, n_item);

    (void)n_in; (void)out_size;
}